// round 2
// baseline (speedup 1.0000x reference)
#include <cuda_runtime.h>
#include <cuda_bf16.h>
#include <math.h>

// ---------------- problem dims ----------------
constexpr int kB = 4, kS = 2048, kD = 512, kH = 8, kDH = 64;
constexpr int kMLP = 2048, kBLK = 128, kNB = 16, kL = 4;
constexpr int kBS = kB * kS;                 // 8192 rows
constexpr int kBSD = kBS * kD;               // 4,194,304
constexpr int kMLPBUF = kBS * kMLP;          // 16,777,216

// ---------------- scratch (static device globals; no allocation) ----------------
static __device__ float g_x[kBSD];
static __device__ float g_h[kBSD];
static __device__ float g_q[kBSD];
static __device__ float g_k[kBSD];
static __device__ float g_v[kBSD];
static __device__ float g_sk[kBSD];
static __device__ float g_sv[kBSD];
static __device__ float g_o[kBSD];
static __device__ float g_mlp[kMLPBUF];
static __device__ float g_ksum[kB * kNB * kD];        // [b,n,h*64+d]
static __device__ float g_perm[kB * kH * kNB * kNB];
static __device__ float g_smask[kB * kH * kNB * kBLK];

// ---------------- embed + positional encoding ----------------
__global__ void embed_pe_kernel(const int* __restrict__ tokens,
                                const float* __restrict__ embed,
                                float* __restrict__ x) {
    int idx = blockIdx.x * 256 + threadIdx.x;
    if (idx >= kBSD) return;
    int d = idx & (kD - 1);
    int bs = idx >> 9;            // kD = 512 = 2^9
    int s = bs & (kS - 1);
    int tok = tokens[bs];
    int i2 = (d >> 1) * 2;
    float freq = expf(-(float)i2 * (logf(10000.0f) / (float)kD));
    float ang = (float)s * freq;
    float pe = (d & 1) ? cosf(ang) : sinf(ang);
    x[idx] = embed[tok * kD + d] + pe;
}

// ---------------- layernorm (row = one token, D=512) ----------------
__global__ __launch_bounds__(128) void ln_kernel(const float* __restrict__ x,
                                                 const float* __restrict__ sc,
                                                 const float* __restrict__ bi,
                                                 float* __restrict__ out) {
    int row = blockIdx.x;
    const float* xp = x + (size_t)row * kD;
    float v[4];
    float s = 0.f, ss = 0.f;
#pragma unroll
    for (int i = 0; i < 4; i++) {
        v[i] = xp[threadIdx.x + i * 128];
        s += v[i];
        ss += v[i] * v[i];
    }
#pragma unroll
    for (int o = 16; o >= 1; o >>= 1) {
        s += __shfl_down_sync(0xffffffffu, s, o);
        ss += __shfl_down_sync(0xffffffffu, ss, o);
    }
    __shared__ float sa[4], sb[4];
    int w = threadIdx.x >> 5;
    if ((threadIdx.x & 31) == 0) { sa[w] = s; sb[w] = ss; }
    __syncthreads();
    s = sa[0] + sa[1] + sa[2] + sa[3];
    ss = sb[0] + sb[1] + sb[2] + sb[3];
    float mean = s * (1.0f / kD);
    float var = ss * (1.0f / kD) - mean * mean;
    float r = rsqrtf(var + 1e-6f);
    float* op = out + (size_t)row * kD;
#pragma unroll
    for (int i = 0; i < 4; i++) {
        int d = threadIdx.x + i * 128;
        op[d] = (v[i] - mean) * r * sc[d] + bi[d];
    }
}

// ---------------- generic SGEMM (double-buffered smem) ----------------
// epi 0: C = alpha*acc
// epi 1: C = gelu(acc + bias)
// epi 2: C = resid + acc + (bias? bias : 0)
__device__ __forceinline__ float gelu_f(float x) {
    const float c = 0.7978845608028654f;
    float x3 = x * x * x;
    return 0.5f * x * (1.0f + tanhf(c * (x + 0.044715f * x3)));
}

__global__ __launch_bounds__(256) void sgemm_kernel(
    int M, int N, int K, float alpha,
    const float* __restrict__ A, const float* __restrict__ Bm,
    const float* __restrict__ bias, const float* __restrict__ resid,
    float* __restrict__ C, int epi) {
    constexpr int BM = 128, BN = 128, BK = 16;
    __shared__ float As[2][BK][BM];
    __shared__ float Bs[2][BK][BN];
    int tid = threadIdx.x;
    int br = blockIdx.y, bc = blockIdx.x;
    const float* Aptr = A + (size_t)br * BM * K;
    const float* Bptr = Bm + (size_t)bc * BN;
    float acc[8][8];
#pragma unroll
    for (int i = 0; i < 8; i++)
#pragma unroll
        for (int j = 0; j < 8; j++) acc[i][j] = 0.f;
    int tr = tid / 16, tc = tid % 16;
    int aRow = tid / 4;
    int aCol = (tid % 4) * 4;
    int bRow = tid / 32;
    int bCol = (tid % 32) * 4;

    // prologue: load tile 0 into buffer 0
    float4 fa0, fa1, fb0, fb1;
    fa0 = *(const float4*)(Aptr + (size_t)aRow * K + aCol);
    fa1 = *(const float4*)(Aptr + (size_t)(aRow + 64) * K + aCol);
    fb0 = *(const float4*)(Bptr + (size_t)bRow * N + bCol);
    fb1 = *(const float4*)(Bptr + (size_t)(bRow + 8) * N + bCol);
    As[0][aCol + 0][aRow] = fa0.x; As[0][aCol + 1][aRow] = fa0.y;
    As[0][aCol + 2][aRow] = fa0.z; As[0][aCol + 3][aRow] = fa0.w;
    As[0][aCol + 0][aRow + 64] = fa1.x; As[0][aCol + 1][aRow + 64] = fa1.y;
    As[0][aCol + 2][aRow + 64] = fa1.z; As[0][aCol + 3][aRow + 64] = fa1.w;
    *(float4*)&Bs[0][bRow][bCol] = fb0;
    *(float4*)&Bs[0][bRow + 8][bCol] = fb1;
    __syncthreads();

    int buf = 0;
    for (int k0 = 0; k0 < K; k0 += BK) {
        int knext = k0 + BK;
        if (knext < K) {
            fa0 = *(const float4*)(Aptr + (size_t)aRow * K + knext + aCol);
            fa1 = *(const float4*)(Aptr + (size_t)(aRow + 64) * K + knext + aCol);
            fb0 = *(const float4*)(Bptr + (size_t)(knext + bRow) * N + bCol);
            fb1 = *(const float4*)(Bptr + (size_t)(knext + bRow + 8) * N + bCol);
        }
#pragma unroll
        for (int kk = 0; kk < BK; kk++) {
            float am[8], bn[8];
            *(float4*)&am[0] = *(const float4*)&As[buf][kk][tr * 8];
            *(float4*)&am[4] = *(const float4*)&As[buf][kk][tr * 8 + 4];
            *(float4*)&bn[0] = *(const float4*)&Bs[buf][kk][tc * 8];
            *(float4*)&bn[4] = *(const float4*)&Bs[buf][kk][tc * 8 + 4];
#pragma unroll
            for (int i = 0; i < 8; i++)
#pragma unroll
                for (int j = 0; j < 8; j++) acc[i][j] += am[i] * bn[j];
        }
        if (knext < K) {
            int nb = buf ^ 1;
            __syncthreads();
            As[nb][aCol + 0][aRow] = fa0.x; As[nb][aCol + 1][aRow] = fa0.y;
            As[nb][aCol + 2][aRow] = fa0.z; As[nb][aCol + 3][aRow] = fa0.w;
            As[nb][aCol + 0][aRow + 64] = fa1.x; As[nb][aCol + 1][aRow + 64] = fa1.y;
            As[nb][aCol + 2][aRow + 64] = fa1.z; As[nb][aCol + 3][aRow + 64] = fa1.w;
            *(float4*)&Bs[nb][bRow][bCol] = fb0;
            *(float4*)&Bs[nb][bRow + 8][bCol] = fb1;
            __syncthreads();
            buf = nb;
        }
    }
    // epilogue
#pragma unroll
    for (int i = 0; i < 8; i++) {
        int row = br * BM + tr * 8 + i;
        int col0 = bc * BN + tc * 8;
        float* cp = C + (size_t)row * N + col0;
        float vr[8];
        if (epi == 0) {
#pragma unroll
            for (int j = 0; j < 8; j++) vr[j] = acc[i][j] * alpha;
        } else if (epi == 1) {
#pragma unroll
            for (int j = 0; j < 8; j++) vr[j] = gelu_f(acc[i][j] + bias[col0 + j]);
        } else {
            const float* rp = resid + (size_t)row * N + col0;
            float4 r0 = *(const float4*)rp;
            float4 r1 = *(const float4*)(rp + 4);
            vr[0] = acc[i][0] + r0.x; vr[1] = acc[i][1] + r0.y;
            vr[2] = acc[i][2] + r0.z; vr[3] = acc[i][3] + r0.w;
            vr[4] = acc[i][4] + r1.x; vr[5] = acc[i][5] + r1.y;
            vr[6] = acc[i][6] + r1.z; vr[7] = acc[i][7] + r1.w;
            if (bias) {
#pragma unroll
                for (int j = 0; j < 8; j++) vr[j] += bias[col0 + j];
            }
        }
        *(float4*)cp = make_float4(vr[0], vr[1], vr[2], vr[3]);
        *(float4*)(cp + 4) = make_float4(vr[4], vr[5], vr[6], vr[7]);
    }
}

// ---------------- ksum: sum of K over each block's 128 positions ----------------
__global__ __launch_bounds__(512) void ksum_kernel(const float* __restrict__ k,
                                                   float* __restrict__ ksum) {
    int bn = blockIdx.x;                  // b*NB + n
    int tid = threadIdx.x;                // = h*64+d
    const float* base = k + (size_t)bn * kBLK * kD + tid;
    float s = 0.f;
#pragma unroll 8
    for (int c = 0; c < kBLK; c++) s += base[(size_t)c * kD];
    ksum[bn * kD + tid] = s;
}

// ---------------- sinkhorn: logits -> 8 iters row/col LSE -> perm, smask ----------------
__global__ __launch_bounds__(256) void sinkhorn_kernel(const float* __restrict__ ksum,
                                                       const float* __restrict__ sw,
                                                       const int* __restrict__ tokens,
                                                       float* __restrict__ perm_out,
                                                       float* __restrict__ smask_out) {
    int b = blockIdx.x / kH, h = blockIdx.x % kH;
    int tid = threadIdx.x;
    int n = tid >> 4, m = tid & 15;
    // logits[n][m] = sum_d ksum[b,n,h,d] * sw[h,d,m]
    const float* kp = ksum + ((size_t)(b * kNB + n)) * kD + h * kDH;
    const float* wp = sw + (size_t)h * kDH * kNB + m;
    float la = 0.f;
#pragma unroll
    for (int d = 0; d < kDH; d++) la += kp[d] * wp[d * kNB];

    __shared__ float sm[16][17];
    for (int it = 0; it < 8; it++) {
        // row logsumexp (over m): 16-lane shfl segments
        float mx = la;
#pragma unroll
        for (int o = 8; o >= 1; o >>= 1)
            mx = fmaxf(mx, __shfl_xor_sync(0xffffffffu, mx, o, 16));
        float e = expf(la - mx);
        float sum = e;
#pragma unroll
        for (int o = 8; o >= 1; o >>= 1)
            sum += __shfl_xor_sync(0xffffffffu, sum, o, 16);
        la = la - (mx + logf(sum));
        // col logsumexp (over n)
        sm[n][m] = la;
        __syncthreads();
        float cmx = -1e30f;
#pragma unroll
        for (int i = 0; i < 16; i++) cmx = fmaxf(cmx, sm[i][m]);
        float cs = 0.f;
#pragma unroll
        for (int i = 0; i < 16; i++) cs += expf(sm[i][m] - cmx);
        la = la - (cmx + logf(cs));
        __syncthreads();
    }
    float p = expf(la);
    sm[n][m] = p;
    perm_out[((size_t)(b * kH + h) * kNB + n) * kNB + m] = p;
    __syncthreads();
    // smask[b,h,n,c] = (sum_m perm[n][m]*mb[b,m,c]) > 0.5
    for (int idx = tid; idx < kNB * kBLK; idx += 256) {
        int nn = idx >> 7, c = idx & 127;
        float s = 0.f;
#pragma unroll
        for (int mm = 0; mm < 16; mm++) {
            float mb = (tokens[b * kS + mm * kBLK + c] > 0) ? 1.f : 0.f;
            s += sm[nn][mm] * mb;
        }
        smask_out[((size_t)(b * kH + h) * kNB + nn) * kBLK + c] = (s > 0.5f) ? 1.f : 0.f;
    }
}

// ---------------- sort-mix: sk/sv = perm @ K/V blocks (reads K,V exactly once) ----------------
__global__ __launch_bounds__(256) void sortmix_kernel(const float* __restrict__ perm,
                                                      const float* __restrict__ k,
                                                      const float* __restrict__ v,
                                                      float* __restrict__ sk,
                                                      float* __restrict__ sv) {
    int chunk = blockIdx.x;   // 16 chunks of 512 over cd=c*64+d (8192 total)
    int h = blockIdx.y;
    int b = blockIdx.z;
    __shared__ float P[16][16];
    __shared__ float T[16][512];
    int tid = threadIdx.x;
    P[tid >> 4][tid & 15] = perm[(size_t)(b * kH + h) * 256 + tid];
    int cd0 = chunk * 512;

    for (int phase = 0; phase < 2; phase++) {
        const float* src = phase ? v : k;
        float* dst = phase ? sv : sk;
        __syncthreads();
        for (int idx = tid; idx < 16 * 512; idx += 256) {
            int m = idx >> 9;
            int j = idx & 511;
            int cd = cd0 + j;
            int c = cd >> 6, d = cd & 63;
            T[m][j] = src[((size_t)(b * kS + m * kBLK + c)) * kD + h * kDH + d];
        }
        __syncthreads();
        for (int idx = tid; idx < 16 * 512; idx += 256) {
            int n = idx >> 9;
            int j = idx & 511;
            float acc = 0.f;
#pragma unroll
            for (int m = 0; m < 16; m++) acc += P[n][m] * T[m][j];
            int cd = cd0 + j;
            int c = cd >> 6, d = cd & 63;
            dst[((size_t)(b * kS + n * kBLK + c)) * kD + h * kDH + d] = acc;
        }
    }
}

// ---------------- attention: per (b,h,n): softmax(Q Kcat^T + bias) Vcat ----------------
__global__ __launch_bounds__(128) void attn_kernel(const float* __restrict__ q,
                                                   const float* __restrict__ k,
                                                   const float* __restrict__ v,
                                                   const float* __restrict__ sk,
                                                   const float* __restrict__ sv,
                                                   const float* __restrict__ smask,
                                                   const int* __restrict__ tokens,
                                                   float* __restrict__ o) {
    int n = blockIdx.x, h = blockIdx.y, b = blockIdx.z;
    int c = threadIdx.x;
    __shared__ float Ks[32][64];
    __shared__ float Vs[32][64];
    __shared__ float biasS[256];
    for (int j = threadIdx.x; j < 256; j += 128) {
        float mv;
        if (j < 128) mv = (tokens[b * kS + n * kBLK + j] > 0) ? 1.f : 0.f;
        else mv = smask[((size_t)(b * kH + h) * kNB + n) * kBLK + (j - 128)];
        biasS[j] = (mv > 0.5f) ? 0.f : -1e9f;
    }
    float qr[64];
    {
        const float4* qp = (const float4*)(q + ((size_t)(b * kS + n * kBLK + c)) * kD + h * kDH);
#pragma unroll
        for (int i = 0; i < 16; i++) {
            float4 t = qp[i];
            qr[4 * i] = t.x; qr[4 * i + 1] = t.y; qr[4 * i + 2] = t.z; qr[4 * i + 3] = t.w;
        }
    }
    float oa[64];
#pragma unroll
    for (int d = 0; d < 64; d++) oa[d] = 0.f;
    float mrun = -1e30f, lrun = 0.f;

    for (int j0 = 0; j0 < 256; j0 += 32) {
        __syncthreads();
        for (int t = threadIdx.x; t < 512; t += 128) {
            int jj = t >> 4;
            int dq = (t & 15) << 2;
            int j = j0 + jj;
            size_t off;
            const float *kb, *vb;
            if (j < 128) {
                off = ((size_t)(b * kS + n * kBLK + j)) * kD + h * kDH + dq;
                kb = k + off; vb = v + off;
            } else {
                off = ((size_t)(b * kS + n * kBLK + (j - 128))) * kD + h * kDH + dq;
                kb = sk + off; vb = sv + off;
            }
            *(float4*)&Ks[jj][dq] = *(const float4*)kb;
            *(float4*)&Vs[jj][dq] = *(const float4*)vb;
        }
        __syncthreads();
        float sreg[32];
        float cmax = -1e30f;
#pragma unroll
        for (int jj = 0; jj < 32; jj++) {
            float s = biasS[j0 + jj];
#pragma unroll
            for (int d = 0; d < 64; d += 4) {
                float4 kv = *(const float4*)&Ks[jj][d];
                s += qr[d] * kv.x + qr[d + 1] * kv.y + qr[d + 2] * kv.z + qr[d + 3] * kv.w;
            }
            sreg[jj] = s;
            cmax = fmaxf(cmax, s);
        }
        float mnew = fmaxf(mrun, cmax);
        float corr = __expf(mrun - mnew);
        lrun *= corr;
#pragma unroll
        for (int d = 0; d < 64; d++) oa[d] *= corr;
#pragma unroll
        for (int jj = 0; jj < 32; jj++) {
            float p = __expf(sreg[jj] - mnew);
            lrun += p;
#pragma unroll
            for (int d = 0; d < 64; d += 4) {
                float4 vv = *(const float4*)&Vs[jj][d];
                oa[d] += p * vv.x; oa[d + 1] += p * vv.y;
                oa[d + 2] += p * vv.z; oa[d + 3] += p * vv.w;
            }
        }
        mrun = mnew;
    }
    float inv = 1.f / lrun;
    float* op = o + ((size_t)(b * kS + n * kBLK + c)) * kD + h * kDH;
#pragma unroll
    for (int d = 0; d < 64; d += 4) {
        *(float4*)(op + d) = make_float4(oa[d] * inv, oa[d + 1] * inv, oa[d + 2] * inv, oa[d + 3] * inv);
    }
}

// ---------------- host orchestration ----------------
extern "C" void kernel_launch(void* const* d_in, const int* in_sizes, int n_in,
                              void* d_out, int out_size) {
    const int* tokens = (const int*)d_in[0];
    const float* embed = (const float*)d_in[1];
    const float* ln1_s = (const float*)d_in[2];
    const float* ln1_b = (const float*)d_in[3];
    const float* wq = (const float*)d_in[4];
    const float* wk = (const float*)d_in[5];
    const float* wv = (const float*)d_in[6];
    const float* wo = (const float*)d_in[7];
    const float* sortw = (const float*)d_in[8];
    const float* ln2_s = (const float*)d_in[9];
    const float* ln2_b = (const float*)d_in[10];
    const float* w1 = (const float*)d_in[11];
    const float* b1 = (const float*)d_in[12];
    const float* w2 = (const float*)d_in[13];
    const float* b2 = (const float*)d_in[14];
    const float* lnf_s = (const float*)d_in[15];
    const float* lnf_b = (const float*)d_in[16];
    float* out = (float*)d_out;

    float *x, *h, *q, *k, *v, *sk, *sv, *o, *mlp, *ksum, *perm, *smask;
    cudaGetSymbolAddress((void**)&x, g_x);
    cudaGetSymbolAddress((void**)&h, g_h);
    cudaGetSymbolAddress((void**)&q, g_q);
    cudaGetSymbolAddress((void**)&k, g_k);
    cudaGetSymbolAddress((void**)&v, g_v);
    cudaGetSymbolAddress((void**)&sk, g_sk);
    cudaGetSymbolAddress((void**)&sv, g_sv);
    cudaGetSymbolAddress((void**)&o, g_o);
    cudaGetSymbolAddress((void**)&mlp, g_mlp);
    cudaGetSymbolAddress((void**)&ksum, g_ksum);
    cudaGetSymbolAddress((void**)&perm, g_perm);
    cudaGetSymbolAddress((void**)&smask, g_smask);

    embed_pe_kernel<<<(kBSD + 255) / 256, 256>>>(tokens, embed, x);

    const float qscale = 1.0f / 8.0f;  // 1/sqrt(64)
    dim3 gD(kD / 128, kBS / 128);       // N=512
    dim3 gM(kMLP / 128, kBS / 128);     // N=2048

    for (int l = 0; l < kL; l++) {
        const float* wq_l = wq + (size_t)l * kD * kD;
        const float* wk_l = wk + (size_t)l * kD * kD;
        const float* wv_l = wv + (size_t)l * kD * kD;
        const float* wo_l = wo + (size_t)l * kD * kD;
        const float* sw_l = sortw + (size_t)l * kH * kDH * kNB;
        const float* w1_l = w1 + (size_t)l * kD * kMLP;
        const float* b1_l = b1 + (size_t)l * kMLP;
        const float* w2_l = w2 + (size_t)l * kMLP * kD;
        const float* b2_l = b2 + (size_t)l * kD;

        ln_kernel<<<kBS, 128>>>(x, ln1_s + l * kD, ln1_b + l * kD, h);
        sgemm_kernel<<<gD, 256>>>(kBS, kD, kD, qscale, h, wq_l, nullptr, nullptr, q, 0);
        sgemm_kernel<<<gD, 256>>>(kBS, kD, kD, 1.0f, h, wk_l, nullptr, nullptr, k, 0);
        sgemm_kernel<<<gD, 256>>>(kBS, kD, kD, 1.0f, h, wv_l, nullptr, nullptr, v, 0);

        ksum_kernel<<<kB * kNB, 512>>>(k, ksum);
        sinkhorn_kernel<<<kB * kH, 256>>>(ksum, sw_l, tokens, perm, smask);
        sortmix_kernel<<<dim3(16, kH, kB), 256>>>(perm, k, v, sk, sv);

        attn_kernel<<<dim3(kNB, kH, kB), 128>>>(q, k, v, sk, sv, smask, tokens, o);

        // x = x + o @ wo
        sgemm_kernel<<<gD, 256>>>(kBS, kD, kD, 1.0f, o, wo_l, nullptr, x, x, 2);

        // MLP
        ln_kernel<<<kBS, 128>>>(x, ln2_s + l * kD, ln2_b + l * kD, h);
        sgemm_kernel<<<gM, 256>>>(kBS, kMLP, kD, 1.0f, h, w1_l, b1_l, nullptr, mlp, 1);
        sgemm_kernel<<<gD, 256>>>(kBS, kD, kMLP, 1.0f, mlp, w2_l, b2_l, x, x, 2);
    }

    ln_kernel<<<kBS, 128>>>(x, lnf_s, lnf_b, out);
}

// round 3
// speedup vs baseline: 1.9686x; 1.9686x over previous
#include <cuda_runtime.h>
#include <cuda_bf16.h>
#include <math.h>
#include <stdint.h>

// ---------------- problem dims ----------------
constexpr int kB = 4, kS = 2048, kD = 512, kH = 8, kDH = 64;
constexpr int kMLP = 2048, kBLK = 128, kNB = 16, kL = 4;
constexpr int kBS = kB * kS;                 // 8192 rows
constexpr int kBSD = kBS * kD;               // 4,194,304
constexpr int kMLPBUF = kBS * kMLP;          // 16,777,216

// ---------------- scratch (static device globals; no allocation) ----------------
static __device__ float g_x[kBSD];
static __device__ float g_h[kBSD];
static __device__ float g_q[kBSD];
static __device__ float g_k[kBSD];
static __device__ float g_v[kBSD];
static __device__ float g_sk[kBSD];
static __device__ float g_sv[kBSD];
static __device__ float g_o[kBSD];
static __device__ float g_mlp[kMLPBUF];
static __device__ float g_ksum[kB * kNB * kD];        // [b,n,h*64+d]
static __device__ float g_perm[kB * kH * kNB * kNB];
static __device__ float g_smask[kB * kH * kNB * kBLK];

// ---------------- embed + positional encoding ----------------
__global__ void embed_pe_kernel(const int* __restrict__ tokens,
                                const float* __restrict__ embed,
                                float* __restrict__ x) {
    int idx = blockIdx.x * 256 + threadIdx.x;
    if (idx >= kBSD) return;
    int d = idx & (kD - 1);
    int bs = idx >> 9;            // kD = 512 = 2^9
    int s = bs & (kS - 1);
    int tok = tokens[bs];
    int i2 = (d >> 1) * 2;
    float freq = expf(-(float)i2 * (logf(10000.0f) / (float)kD));
    float ang = (float)s * freq;
    float pe = (d & 1) ? cosf(ang) : sinf(ang);
    x[idx] = embed[tok * kD + d] + pe;
}

// ---------------- layernorm (row = one token, D=512) ----------------
__global__ __launch_bounds__(128) void ln_kernel(const float* __restrict__ x,
                                                 const float* __restrict__ sc,
                                                 const float* __restrict__ bi,
                                                 float* __restrict__ out) {
    int row = blockIdx.x;
    const float* xp = x + (size_t)row * kD;
    float v[4];
    float s = 0.f, ss = 0.f;
#pragma unroll
    for (int i = 0; i < 4; i++) {
        v[i] = xp[threadIdx.x + i * 128];
        s += v[i];
        ss += v[i] * v[i];
    }
#pragma unroll
    for (int o = 16; o >= 1; o >>= 1) {
        s += __shfl_down_sync(0xffffffffu, s, o);
        ss += __shfl_down_sync(0xffffffffu, ss, o);
    }
    __shared__ float sa[4], sb[4];
    int w = threadIdx.x >> 5;
    if ((threadIdx.x & 31) == 0) { sa[w] = s; sb[w] = ss; }
    __syncthreads();
    s = sa[0] + sa[1] + sa[2] + sa[3];
    ss = sb[0] + sb[1] + sb[2] + sb[3];
    float mean = s * (1.0f / kD);
    float var = ss * (1.0f / kD) - mean * mean;
    float r = rsqrtf(var + 1e-6f);
    float* op = out + (size_t)row * kD;
#pragma unroll
    for (int i = 0; i < 4; i++) {
        int d = threadIdx.x + i * 128;
        op[d] = (v[i] - mean) * r * sc[d] + bi[d];
    }
}

// ---------------- TF32 tensor-core GEMM ----------------
// epi 0: C = alpha*acc
// epi 1: C = gelu(acc + bias)
// epi 2: C = resid + acc + (bias? bias : 0)
__device__ __forceinline__ float gelu_f(float x) {
    const float c = 0.7978845608028654f;
    float x3 = x * x * x;
    return 0.5f * x * (1.0f + tanhf(c * (x + 0.044715f * x3)));
}

__device__ __forceinline__ uint32_t to_tf32(float x) {
    uint32_t u;
    asm("cvt.rna.tf32.f32 %0, %1;" : "=r"(u) : "f"(x));
    return u;
}

__device__ __forceinline__ void mma_tf32(float* c, uint32_t a0, uint32_t a1,
                                         uint32_t a2, uint32_t a3,
                                         uint32_t b0, uint32_t b1) {
    asm volatile(
        "mma.sync.aligned.m16n8k8.row.col.f32.tf32.tf32.f32 "
        "{%0,%1,%2,%3}, {%4,%5,%6,%7}, {%8,%9}, {%0,%1,%2,%3};"
        : "+f"(c[0]), "+f"(c[1]), "+f"(c[2]), "+f"(c[3])
        : "r"(a0), "r"(a1), "r"(a2), "r"(a3), "r"(b0), "r"(b1));
}

__global__ __launch_bounds__(256, 2) void tgemm_kernel(
    int M, int N, int K, float alpha,
    const float* __restrict__ A, const float* __restrict__ Bm,
    const float* __restrict__ bias, const float* __restrict__ resid,
    float* __restrict__ C, int epi) {
    constexpr int BM = 128, BN = 128, BK = 16;
    constexpr int LDA = BM + 4, LDB = BN + 4;
    __shared__ uint32_t As[2][BK][LDA];
    __shared__ uint32_t Bs[2][BK][LDB];
    int tid = threadIdx.x;
    int lane = tid & 31;
    int w = tid >> 5;
    int wr = w >> 2, wc = w & 3;       // 2x4 warp grid; warp tile 64x32
    int br = blockIdx.y, bc = blockIdx.x;
    const float* Aptr = A + (size_t)br * BM * K;
    const float* Bptr = Bm + (size_t)bc * BN;

    float acc[4][4][4];
#pragma unroll
    for (int i = 0; i < 4; i++)
#pragma unroll
        for (int j = 0; j < 4; j++)
#pragma unroll
            for (int r = 0; r < 4; r++) acc[i][j][r] = 0.f;

    int aRow = tid >> 2;            // 0..63
    int aCol = (tid & 3) * 4;
    int bRow = tid >> 5;            // 0..7
    int bCol = (tid & 31) * 4;

    int lq = lane >> 2;             // lane/4: 0..7
    int lr = lane & 3;              // lane%4: 0..3

    float4 fa0, fa1, fb0, fb1;
    // prologue: tile 0 -> buffer 0
    fa0 = *(const float4*)(Aptr + (size_t)aRow * K + aCol);
    fa1 = *(const float4*)(Aptr + (size_t)(aRow + 64) * K + aCol);
    fb0 = *(const float4*)(Bptr + (size_t)bRow * N + bCol);
    fb1 = *(const float4*)(Bptr + (size_t)(bRow + 8) * N + bCol);
    As[0][aCol + 0][aRow] = to_tf32(fa0.x); As[0][aCol + 1][aRow] = to_tf32(fa0.y);
    As[0][aCol + 2][aRow] = to_tf32(fa0.z); As[0][aCol + 3][aRow] = to_tf32(fa0.w);
    As[0][aCol + 0][aRow + 64] = to_tf32(fa1.x); As[0][aCol + 1][aRow + 64] = to_tf32(fa1.y);
    As[0][aCol + 2][aRow + 64] = to_tf32(fa1.z); As[0][aCol + 3][aRow + 64] = to_tf32(fa1.w);
    Bs[0][bRow][bCol + 0] = to_tf32(fb0.x); Bs[0][bRow][bCol + 1] = to_tf32(fb0.y);
    Bs[0][bRow][bCol + 2] = to_tf32(fb0.z); Bs[0][bRow][bCol + 3] = to_tf32(fb0.w);
    Bs[0][bRow + 8][bCol + 0] = to_tf32(fb1.x); Bs[0][bRow + 8][bCol + 1] = to_tf32(fb1.y);
    Bs[0][bRow + 8][bCol + 2] = to_tf32(fb1.z); Bs[0][bRow + 8][bCol + 3] = to_tf32(fb1.w);
    __syncthreads();

    int buf = 0;
    for (int k0 = 0; k0 < K; k0 += BK) {
        int knext = k0 + BK;
        if (knext < K) {
            fa0 = *(const float4*)(Aptr + (size_t)aRow * K + knext + aCol);
            fa1 = *(const float4*)(Aptr + (size_t)(aRow + 64) * K + knext + aCol);
            fb0 = *(const float4*)(Bptr + (size_t)(knext + bRow) * N + bCol);
            fb1 = *(const float4*)(Bptr + (size_t)(knext + bRow + 8) * N + bCol);
        }
#pragma unroll
        for (int ks = 0; ks < BK; ks += 8) {
            uint32_t bfr[4][2];
#pragma unroll
            for (int j = 0; j < 4; j++) {
                int n0 = wc * 32 + j * 8 + lq;
                bfr[j][0] = Bs[buf][ks + lr][n0];
                bfr[j][1] = Bs[buf][ks + lr + 4][n0];
            }
#pragma unroll
            for (int i = 0; i < 4; i++) {
                int m0 = wr * 64 + i * 16 + lq;
                uint32_t a0 = As[buf][ks + lr][m0];
                uint32_t a1 = As[buf][ks + lr][m0 + 8];
                uint32_t a2 = As[buf][ks + lr + 4][m0];
                uint32_t a3 = As[buf][ks + lr + 4][m0 + 8];
#pragma unroll
                for (int j = 0; j < 4; j++)
                    mma_tf32(acc[i][j], a0, a1, a2, a3, bfr[j][0], bfr[j][1]);
            }
        }
        if (knext < K) {
            int nb = buf ^ 1;
            __syncthreads();
            As[nb][aCol + 0][aRow] = to_tf32(fa0.x); As[nb][aCol + 1][aRow] = to_tf32(fa0.y);
            As[nb][aCol + 2][aRow] = to_tf32(fa0.z); As[nb][aCol + 3][aRow] = to_tf32(fa0.w);
            As[nb][aCol + 0][aRow + 64] = to_tf32(fa1.x); As[nb][aCol + 1][aRow + 64] = to_tf32(fa1.y);
            As[nb][aCol + 2][aRow + 64] = to_tf32(fa1.z); As[nb][aCol + 3][aRow + 64] = to_tf32(fa1.w);
            Bs[nb][bRow][bCol + 0] = to_tf32(fb0.x); Bs[nb][bRow][bCol + 1] = to_tf32(fb0.y);
            Bs[nb][bRow][bCol + 2] = to_tf32(fb0.z); Bs[nb][bRow][bCol + 3] = to_tf32(fb0.w);
            Bs[nb][bRow + 8][bCol + 0] = to_tf32(fb1.x); Bs[nb][bRow + 8][bCol + 1] = to_tf32(fb1.y);
            Bs[nb][bRow + 8][bCol + 2] = to_tf32(fb1.z); Bs[nb][bRow + 8][bCol + 3] = to_tf32(fb1.w);
            __syncthreads();
            buf = nb;
        }
    }

    // epilogue: each (i,j) tile -> rows {r0, r0+8}, cols col..col+1
#pragma unroll
    for (int i = 0; i < 4; i++) {
        int r0 = br * BM + wr * 64 + i * 16 + lq;
#pragma unroll
        for (int j = 0; j < 4; j++) {
            int col = bc * BN + wc * 32 + j * 8 + lr * 2;
#pragma unroll
            for (int half = 0; half < 2; half++) {
                int row = r0 + half * 8;
                float v0 = acc[i][j][half * 2 + 0];
                float v1 = acc[i][j][half * 2 + 1];
                float* cp = C + (size_t)row * N + col;
                if (epi == 0) {
                    v0 *= alpha; v1 *= alpha;
                } else if (epi == 1) {
                    v0 = gelu_f(v0 + bias[col]);
                    v1 = gelu_f(v1 + bias[col + 1]);
                } else {
                    const float* rp = resid + (size_t)row * N + col;
                    float2 rr = *(const float2*)rp;
                    v0 += rr.x; v1 += rr.y;
                    if (bias) { v0 += bias[col]; v1 += bias[col + 1]; }
                }
                *(float2*)cp = make_float2(v0, v1);
            }
        }
    }
}

// ---------------- ksum: sum of K over each block's 128 positions ----------------
__global__ __launch_bounds__(512) void ksum_kernel(const float* __restrict__ k,
                                                   float* __restrict__ ksum) {
    int bn = blockIdx.x;                  // b*NB + n
    int tid = threadIdx.x;                // = h*64+d
    const float* base = k + (size_t)bn * kBLK * kD + tid;
    float s = 0.f;
#pragma unroll 8
    for (int c = 0; c < kBLK; c++) s += base[(size_t)c * kD];
    ksum[bn * kD + tid] = s;
}

// ---------------- sinkhorn: logits -> 8 iters row/col LSE -> perm, smask ----------------
__global__ __launch_bounds__(256) void sinkhorn_kernel(const float* __restrict__ ksum,
                                                       const float* __restrict__ sw,
                                                       const int* __restrict__ tokens,
                                                       float* __restrict__ perm_out,
                                                       float* __restrict__ smask_out) {
    int b = blockIdx.x / kH, h = blockIdx.x % kH;
    int tid = threadIdx.x;
    int n = tid >> 4, m = tid & 15;
    const float* kp = ksum + ((size_t)(b * kNB + n)) * kD + h * kDH;
    const float* wp = sw + (size_t)h * kDH * kNB + m;
    float la = 0.f;
#pragma unroll
    for (int d = 0; d < kDH; d++) la += kp[d] * wp[d * kNB];

    __shared__ float sm[16][17];
    for (int it = 0; it < 8; it++) {
        float mx = la;
#pragma unroll
        for (int o = 8; o >= 1; o >>= 1)
            mx = fmaxf(mx, __shfl_xor_sync(0xffffffffu, mx, o, 16));
        float e = expf(la - mx);
        float sum = e;
#pragma unroll
        for (int o = 8; o >= 1; o >>= 1)
            sum += __shfl_xor_sync(0xffffffffu, sum, o, 16);
        la = la - (mx + logf(sum));
        sm[n][m] = la;
        __syncthreads();
        float cmx = -1e30f;
#pragma unroll
        for (int i = 0; i < 16; i++) cmx = fmaxf(cmx, sm[i][m]);
        float cs = 0.f;
#pragma unroll
        for (int i = 0; i < 16; i++) cs += expf(sm[i][m] - cmx);
        la = la - (cmx + logf(cs));
        __syncthreads();
    }
    float p = expf(la);
    sm[n][m] = p;
    perm_out[((size_t)(b * kH + h) * kNB + n) * kNB + m] = p;
    __syncthreads();
    for (int idx = tid; idx < kNB * kBLK; idx += 256) {
        int nn = idx >> 7, c = idx & 127;
        float s = 0.f;
#pragma unroll
        for (int mm = 0; mm < 16; mm++) {
            float mb = (tokens[b * kS + mm * kBLK + c] > 0) ? 1.f : 0.f;
            s += sm[nn][mm] * mb;
        }
        smask_out[((size_t)(b * kH + h) * kNB + nn) * kBLK + c] = (s > 0.5f) ? 1.f : 0.f;
    }
}

// ---------------- sort-mix: sk/sv = perm @ K/V blocks ----------------
__global__ __launch_bounds__(256) void sortmix_kernel(const float* __restrict__ perm,
                                                      const float* __restrict__ k,
                                                      const float* __restrict__ v,
                                                      float* __restrict__ sk,
                                                      float* __restrict__ sv) {
    int chunk = blockIdx.x;
    int h = blockIdx.y;
    int b = blockIdx.z;
    __shared__ float P[16][16];
    __shared__ float T[16][512];
    int tid = threadIdx.x;
    P[tid >> 4][tid & 15] = perm[(size_t)(b * kH + h) * 256 + tid];
    int cd0 = chunk * 512;

    for (int phase = 0; phase < 2; phase++) {
        const float* src = phase ? v : k;
        float* dst = phase ? sv : sk;
        __syncthreads();
        for (int idx = tid; idx < 16 * 512; idx += 256) {
            int m = idx >> 9;
            int j = idx & 511;
            int cd = cd0 + j;
            int c = cd >> 6, d = cd & 63;
            T[m][j] = src[((size_t)(b * kS + m * kBLK + c)) * kD + h * kDH + d];
        }
        __syncthreads();
        for (int idx = tid; idx < 16 * 512; idx += 256) {
            int n = idx >> 9;
            int j = idx & 511;
            float acc = 0.f;
#pragma unroll
            for (int m = 0; m < 16; m++) acc += P[n][m] * T[m][j];
            int cd = cd0 + j;
            int c = cd >> 6, d = cd & 63;
            dst[((size_t)(b * kS + n * kBLK + c)) * kD + h * kDH + d] = acc;
        }
    }
}

// ---------------- attention: per (b,h,n): softmax(Q Kcat^T + bias) Vcat ----------------
__global__ __launch_bounds__(128) void attn_kernel(const float* __restrict__ q,
                                                   const float* __restrict__ k,
                                                   const float* __restrict__ v,
                                                   const float* __restrict__ sk,
                                                   const float* __restrict__ sv,
                                                   const float* __restrict__ smask,
                                                   const int* __restrict__ tokens,
                                                   float* __restrict__ o) {
    int n = blockIdx.x, h = blockIdx.y, b = blockIdx.z;
    int c = threadIdx.x;
    __shared__ float Ks[32][64];
    __shared__ float Vs[32][64];
    __shared__ float biasS[256];
    for (int j = threadIdx.x; j < 256; j += 128) {
        float mv;
        if (j < 128) mv = (tokens[b * kS + n * kBLK + j] > 0) ? 1.f : 0.f;
        else mv = smask[((size_t)(b * kH + h) * kNB + n) * kBLK + (j - 128)];
        biasS[j] = (mv > 0.5f) ? 0.f : -1e9f;
    }
    float qr[64];
    {
        const float4* qp = (const float4*)(q + ((size_t)(b * kS + n * kBLK + c)) * kD + h * kDH);
#pragma unroll
        for (int i = 0; i < 16; i++) {
            float4 t = qp[i];
            qr[4 * i] = t.x; qr[4 * i + 1] = t.y; qr[4 * i + 2] = t.z; qr[4 * i + 3] = t.w;
        }
    }
    float oa[64];
#pragma unroll
    for (int d = 0; d < 64; d++) oa[d] = 0.f;
    float mrun = -1e30f, lrun = 0.f;

    for (int j0 = 0; j0 < 256; j0 += 32) {
        __syncthreads();
        for (int t = threadIdx.x; t < 512; t += 128) {
            int jj = t >> 4;
            int dq = (t & 15) << 2;
            int j = j0 + jj;
            size_t off;
            const float *kb, *vb;
            if (j < 128) {
                off = ((size_t)(b * kS + n * kBLK + j)) * kD + h * kDH + dq;
                kb = k + off; vb = v + off;
            } else {
                off = ((size_t)(b * kS + n * kBLK + (j - 128))) * kD + h * kDH + dq;
                kb = sk + off; vb = sv + off;
            }
            *(float4*)&Ks[jj][dq] = *(const float4*)kb;
            *(float4*)&Vs[jj][dq] = *(const float4*)vb;
        }
        __syncthreads();
        float sreg[32];
        float cmax = -1e30f;
#pragma unroll
        for (int jj = 0; jj < 32; jj++) {
            float s = biasS[j0 + jj];
#pragma unroll
            for (int d = 0; d < 64; d += 4) {
                float4 kv = *(const float4*)&Ks[jj][d];
                s += qr[d] * kv.x + qr[d + 1] * kv.y + qr[d + 2] * kv.z + qr[d + 3] * kv.w;
            }
            sreg[jj] = s;
            cmax = fmaxf(cmax, s);
        }
        float mnew = fmaxf(mrun, cmax);
        float corr = __expf(mrun - mnew);
        lrun *= corr;
#pragma unroll
        for (int d = 0; d < 64; d++) oa[d] *= corr;
#pragma unroll
        for (int jj = 0; jj < 32; jj++) {
            float p = __expf(sreg[jj] - mnew);
            lrun += p;
#pragma unroll
            for (int d = 0; d < 64; d += 4) {
                float4 vv = *(const float4*)&Vs[jj][d];
                oa[d] += p * vv.x; oa[d + 1] += p * vv.y;
                oa[d + 2] += p * vv.z; oa[d + 3] += p * vv.w;
            }
        }
        mrun = mnew;
    }
    float inv = 1.f / lrun;
    float* op = o + ((size_t)(b * kS + n * kBLK + c)) * kD + h * kDH;
#pragma unroll
    for (int d = 0; d < 64; d += 4) {
        *(float4*)(op + d) = make_float4(oa[d] * inv, oa[d + 1] * inv, oa[d + 2] * inv, oa[d + 3] * inv);
    }
}

// ---------------- host orchestration ----------------
extern "C" void kernel_launch(void* const* d_in, const int* in_sizes, int n_in,
                              void* d_out, int out_size) {
    const int* tokens = (const int*)d_in[0];
    const float* embed = (const float*)d_in[1];
    const float* ln1_s = (const float*)d_in[2];
    const float* ln1_b = (const float*)d_in[3];
    const float* wq = (const float*)d_in[4];
    const float* wk = (const float*)d_in[5];
    const float* wv = (const float*)d_in[6];
    const float* wo = (const float*)d_in[7];
    const float* sortw = (const float*)d_in[8];
    const float* ln2_s = (const float*)d_in[9];
    const float* ln2_b = (const float*)d_in[10];
    const float* w1 = (const float*)d_in[11];
    const float* b1 = (const float*)d_in[12];
    const float* w2 = (const float*)d_in[13];
    const float* b2 = (const float*)d_in[14];
    const float* lnf_s = (const float*)d_in[15];
    const float* lnf_b = (const float*)d_in[16];
    float* out = (float*)d_out;

    float *x, *h, *q, *k, *v, *sk, *sv, *o, *mlp, *ksum, *perm, *smask;
    cudaGetSymbolAddress((void**)&x, g_x);
    cudaGetSymbolAddress((void**)&h, g_h);
    cudaGetSymbolAddress((void**)&q, g_q);
    cudaGetSymbolAddress((void**)&k, g_k);
    cudaGetSymbolAddress((void**)&v, g_v);
    cudaGetSymbolAddress((void**)&sk, g_sk);
    cudaGetSymbolAddress((void**)&sv, g_sv);
    cudaGetSymbolAddress((void**)&o, g_o);
    cudaGetSymbolAddress((void**)&mlp, g_mlp);
    cudaGetSymbolAddress((void**)&ksum, g_ksum);
    cudaGetSymbolAddress((void**)&perm, g_perm);
    cudaGetSymbolAddress((void**)&smask, g_smask);

    embed_pe_kernel<<<(kBSD + 255) / 256, 256>>>(tokens, embed, x);

    const float qscale = 1.0f / 8.0f;  // 1/sqrt(64)
    dim3 gD(kD / 128, kBS / 128);       // N=512
    dim3 gM(kMLP / 128, kBS / 128);     // N=2048

    for (int l = 0; l < kL; l++) {
        const float* wq_l = wq + (size_t)l * kD * kD;
        const float* wk_l = wk + (size_t)l * kD * kD;
        const float* wv_l = wv + (size_t)l * kD * kD;
        const float* wo_l = wo + (size_t)l * kD * kD;
        const float* sw_l = sortw + (size_t)l * kH * kDH * kNB;
        const float* w1_l = w1 + (size_t)l * kD * kMLP;
        const float* b1_l = b1 + (size_t)l * kMLP;
        const float* w2_l = w2 + (size_t)l * kMLP * kD;
        const float* b2_l = b2 + (size_t)l * kD;

        ln_kernel<<<kBS, 128>>>(x, ln1_s + l * kD, ln1_b + l * kD, h);
        tgemm_kernel<<<gD, 256>>>(kBS, kD, kD, qscale, h, wq_l, nullptr, nullptr, q, 0);
        tgemm_kernel<<<gD, 256>>>(kBS, kD, kD, 1.0f, h, wk_l, nullptr, nullptr, k, 0);
        tgemm_kernel<<<gD, 256>>>(kBS, kD, kD, 1.0f, h, wv_l, nullptr, nullptr, v, 0);

        ksum_kernel<<<kB * kNB, 512>>>(k, ksum);
        sinkhorn_kernel<<<kB * kH, 256>>>(ksum, sw_l, tokens, perm, smask);
        sortmix_kernel<<<dim3(16, kH, kB), 256>>>(perm, k, v, sk, sv);

        attn_kernel<<<dim3(kNB, kH, kB), 128>>>(q, k, v, sk, sv, smask, tokens, o);

        // x = x + o @ wo
        tgemm_kernel<<<gD, 256>>>(kBS, kD, kD, 1.0f, o, wo_l, nullptr, x, x, 2);

        // MLP
        ln_kernel<<<kBS, 128>>>(x, ln2_s + l * kD, ln2_b + l * kD, h);
        tgemm_kernel<<<gM, 256>>>(kBS, kMLP, kD, 1.0f, h, w1_l, b1_l, nullptr, mlp, 1);
        tgemm_kernel<<<gD, 256>>>(kBS, kD, kMLP, 1.0f, mlp, w2_l, b2_l, x, x, 2);
    }

    ln_kernel<<<kBS, 128>>>(x, lnf_s, lnf_b, out);
}

// round 5
// speedup vs baseline: 3.1902x; 1.6205x over previous
#include <cuda_runtime.h>
#include <cuda_fp16.h>
#include <math.h>
#include <stdint.h>

// ---------------- problem dims ----------------
constexpr int kB = 4, kS = 2048, kD = 512, kH = 8, kDH = 64;
constexpr int kMLP = 2048, kBLK = 128, kNB = 16, kL = 4;
constexpr int kBS = kB * kS;                 // 8192 rows
constexpr int kBSD = kBS * kD;               // 4,194,304

// ---------------- scratch (static device globals; no allocation) ----------------
static __device__ float g_x[kBSD];
static __device__ float g_q[kBSD];
static __device__ float g_k[kBSD];
static __device__ float g_v[kBSD];
static __device__ float g_sk[kBSD];
static __device__ float g_sv[kBSD];
static __device__ __align__(256) __half g_hh[kBSD];          // LN outputs (fp16)
static __device__ __align__(256) __half g_oh[kBSD];          // attention out (fp16)
static __device__ __align__(256) __half g_mlph[kBS * kMLP];  // gelu out (fp16)
static __device__ __align__(256) __half g_wq_h[kL * kD * kD];
static __device__ __align__(256) __half g_wk_h[kL * kD * kD];
static __device__ __align__(256) __half g_wv_h[kL * kD * kD];
static __device__ __align__(256) __half g_wo_h[kL * kD * kD];
static __device__ __align__(256) __half g_w1_h[kL * kD * kMLP];
static __device__ __align__(256) __half g_w2_h[kL * kMLP * kD];
static __device__ float g_ksum[kB * kNB * kD];
static __device__ float g_perm[kB * kH * kNB * kNB];
static __device__ float g_smask[kB * kH * kNB * kBLK];

// ---------------- fp32 -> fp16 bulk convert ----------------
__global__ void f2h_kernel(const float* __restrict__ s, __half* __restrict__ d, int n) {
    int i = (blockIdx.x * 256 + threadIdx.x) * 4;
    if (i >= n) return;
    float4 f = *(const float4*)(s + i);
    __half2* dp = (__half2*)(d + i);
    dp[0] = __floats2half2_rn(f.x, f.y);
    dp[1] = __floats2half2_rn(f.z, f.w);
}

// ---------------- embed + positional encoding ----------------
__global__ void embed_pe_kernel(const int* __restrict__ tokens,
                                const float* __restrict__ embed,
                                float* __restrict__ x) {
    int idx = blockIdx.x * 256 + threadIdx.x;
    if (idx >= kBSD) return;
    int d = idx & (kD - 1);
    int bs = idx >> 9;
    int s = bs & (kS - 1);
    int tok = tokens[bs];
    int i2 = (d >> 1) * 2;
    float freq = expf(-(float)i2 * (logf(10000.0f) / (float)kD));
    float ang = (float)s * freq;
    float pe = (d & 1) ? cosf(ang) : sinf(ang);
    x[idx] = embed[tok * kD + d] + pe;
}

// ---------------- layernorm: fp32 in, fp16 out (or fp32 for final) ----------------
__global__ __launch_bounds__(128) void ln_kernel(const float* __restrict__ x,
                                                 const float* __restrict__ sc,
                                                 const float* __restrict__ bi,
                                                 __half* __restrict__ outh,
                                                 float* __restrict__ outf) {
    int row = blockIdx.x;
    const float* xp = x + (size_t)row * kD;
    float v[4];
    float s = 0.f, ss = 0.f;
#pragma unroll
    for (int i = 0; i < 4; i++) {
        v[i] = xp[threadIdx.x + i * 128];
        s += v[i];
        ss += v[i] * v[i];
    }
#pragma unroll
    for (int o = 16; o >= 1; o >>= 1) {
        s += __shfl_down_sync(0xffffffffu, s, o);
        ss += __shfl_down_sync(0xffffffffu, ss, o);
    }
    __shared__ float sa[4], sb[4];
    int w = threadIdx.x >> 5;
    if ((threadIdx.x & 31) == 0) { sa[w] = s; sb[w] = ss; }
    __syncthreads();
    s = sa[0] + sa[1] + sa[2] + sa[3];
    ss = sb[0] + sb[1] + sb[2] + sb[3];
    float mean = s * (1.0f / kD);
    float var = ss * (1.0f / kD) - mean * mean;
    float r = rsqrtf(var + 1e-6f);
#pragma unroll
    for (int i = 0; i < 4; i++) {
        int d = threadIdx.x + i * 128;
        float o = (v[i] - mean) * r * sc[d] + bi[d];
        if (outh) outh[(size_t)row * kD + d] = __float2half_rn(o);
        else outf[(size_t)row * kD + d] = o;
    }
}

// ---------------- fp16 tensor-core GEMM ----------------
__device__ __forceinline__ float gelu_f(float x) {
    const float c = 0.7978845608028654f;
    float x3 = x * x * x;
    return 0.5f * x * (1.0f + tanhf(c * (x + 0.044715f * x3)));
}

__device__ __forceinline__ uint32_t smem_u32(const void* p) {
    return (uint32_t)__cvta_generic_to_shared(p);
}
__device__ __forceinline__ void ldsm_x4(uint32_t& r0, uint32_t& r1, uint32_t& r2,
                                        uint32_t& r3, uint32_t addr) {
    asm volatile("ldmatrix.sync.aligned.m8n8.x4.shared.b16 {%0,%1,%2,%3},[%4];"
                 : "=r"(r0), "=r"(r1), "=r"(r2), "=r"(r3) : "r"(addr));
}
__device__ __forceinline__ void ldsm_x4t(uint32_t& r0, uint32_t& r1, uint32_t& r2,
                                         uint32_t& r3, uint32_t addr) {
    asm volatile("ldmatrix.sync.aligned.m8n8.x4.trans.shared.b16 {%0,%1,%2,%3},[%4];"
                 : "=r"(r0), "=r"(r1), "=r"(r2), "=r"(r3) : "r"(addr));
}
__device__ __forceinline__ void mma_f16(float* c, uint32_t a0, uint32_t a1,
                                        uint32_t a2, uint32_t a3,
                                        uint32_t b0, uint32_t b1) {
    asm volatile(
        "mma.sync.aligned.m16n8k16.row.col.f32.f16.f16.f32 "
        "{%0,%1,%2,%3},{%4,%5,%6,%7},{%8,%9},{%0,%1,%2,%3};"
        : "+f"(c[0]), "+f"(c[1]), "+f"(c[2]), "+f"(c[3])
        : "r"(a0), "r"(a1), "r"(a2), "r"(a3), "r"(b0), "r"(b1));
}
__device__ __forceinline__ void cp16(uint32_t dst, const void* src) {
    asm volatile("cp.async.cg.shared.global [%0],[%1],16;" :: "r"(dst), "l"(src));
}

// epi 0: Cf = alpha*acc
// epi 1: Ch = gelu(acc + bias)
// epi 2: Cf = resid + acc + (bias? bias : 0)
__global__ __launch_bounds__(256, 2) void hgemm_kernel(
    int M, int N, int K, float alpha,
    const __half* __restrict__ A, const __half* __restrict__ Bm,
    const float* __restrict__ bias, const float* __restrict__ resid,
    float* __restrict__ Cf, __half* __restrict__ Ch, int epi) {
    constexpr int BM = 128, BN = 128, BK = 32;
    constexpr int AP = 40, BP = 136;   // pitches in halves (80B / 272B) - LDSM conflict-free
    __shared__ __half As[2][BM * AP];
    __shared__ __half Bs[2][BK * BP];
    int tid = threadIdx.x, lane = tid & 31, w = tid >> 5;
    int wr = w >> 2, wc = w & 3;       // 2x4 warp grid, warp tile 64x32
    int br = blockIdx.y, bc = blockIdx.x;
    const __half* Ap = A + (size_t)br * BM * K;
    const __half* Bp = Bm + (size_t)bc * BN;

    float acc[4][4][4];
#pragma unroll
    for (int i = 0; i < 4; i++)
#pragma unroll
        for (int j = 0; j < 4; j++)
#pragma unroll
            for (int r = 0; r < 4; r++) acc[i][j][r] = 0.f;

    int arow = tid >> 2, achk = tid & 3;     // A: 64 rows/pass, 4 chunks of 8 halves
    int brow = tid >> 4, bchk = tid & 15;    // B: 16 rows/pass, 16 chunks

    auto issue = [&](int buf, int k0) {
        uint32_t ab = smem_u32(&As[buf][0]);
        uint32_t bb = smem_u32(&Bs[buf][0]);
#pragma unroll
        for (int p = 0; p < 2; p++) {
            int r = arow + p * 64;
            cp16(ab + (uint32_t)(r * AP + achk * 8) * 2, Ap + (size_t)r * K + k0 + achk * 8);
        }
#pragma unroll
        for (int p = 0; p < 2; p++) {
            int r = brow + p * 16;
            cp16(bb + (uint32_t)(r * BP + bchk * 8) * 2, Bp + (size_t)(k0 + r) * N + bchk * 8);
        }
        asm volatile("cp.async.commit_group;");
    };

    int nt = K / BK;
    issue(0, 0);
    int rowoff = (lane & 7) + ((lane >> 3) & 1) * 8;
    int seloff = (lane >> 4) * 8;

    for (int t = 0; t < nt; t++) {
        if (t + 1 < nt) {
            issue((t + 1) & 1, (t + 1) * BK);
            asm volatile("cp.async.wait_group 1;");
        } else {
            asm volatile("cp.async.wait_group 0;");
        }
        __syncthreads();
        int buf = t & 1;
#pragma unroll
        for (int s = 0; s < 2; s++) {
            int k0 = s * 16;
            uint32_t af[4][4], bf[4][2];
#pragma unroll
            for (int i = 0; i < 4; i++) {
                int m0 = wr * 64 + i * 16;
                uint32_t addr = smem_u32(&As[buf][(m0 + rowoff) * AP + k0 + seloff]);
                ldsm_x4(af[i][0], af[i][1], af[i][2], af[i][3], addr);
            }
#pragma unroll
            for (int j2 = 0; j2 < 2; j2++) {
                int n0 = wc * 32 + j2 * 16;
                uint32_t addr = smem_u32(&Bs[buf][(k0 + rowoff) * BP + n0 + seloff]);
                uint32_t r0, r1, r2, r3;
                ldsm_x4t(r0, r1, r2, r3, addr);
                bf[j2 * 2][0] = r0; bf[j2 * 2][1] = r1;
                bf[j2 * 2 + 1][0] = r2; bf[j2 * 2 + 1][1] = r3;
            }
#pragma unroll
            for (int i = 0; i < 4; i++)
#pragma unroll
                for (int j = 0; j < 4; j++)
                    mma_f16(acc[i][j], af[i][0], af[i][1], af[i][2], af[i][3],
                            bf[j][0], bf[j][1]);
        }
        __syncthreads();
    }

    int lq = lane >> 2, lr = lane & 3;
#pragma unroll
    for (int i = 0; i < 4; i++) {
        int r0 = br * BM + wr * 64 + i * 16 + lq;
#pragma unroll
        for (int j = 0; j < 4; j++) {
            int col = bc * BN + wc * 32 + j * 8 + lr * 2;
#pragma unroll
            for (int half = 0; half < 2; half++) {
                int row = r0 + half * 8;
                float v0 = acc[i][j][half * 2 + 0];
                float v1 = acc[i][j][half * 2 + 1];
                if (epi == 0) {
                    v0 *= alpha; v1 *= alpha;
                    *(float2*)(Cf + (size_t)row * N + col) = make_float2(v0, v1);
                } else if (epi == 1) {
                    v0 = gelu_f(v0 + bias[col]);
                    v1 = gelu_f(v1 + bias[col + 1]);
                    *(__half2*)(Ch + (size_t)row * N + col) = __floats2half2_rn(v0, v1);
                } else {
                    const float* rp = resid + (size_t)row * N + col;
                    float2 rr = *(const float2*)rp;
                    v0 += rr.x; v1 += rr.y;
                    if (bias) { v0 += bias[col]; v1 += bias[col + 1]; }
                    *(float2*)(Cf + (size_t)row * N + col) = make_float2(v0, v1);
                }
            }
        }
    }
}

// ---------------- ksum ----------------
__global__ __launch_bounds__(512) void ksum_kernel(const float* __restrict__ k,
                                                   float* __restrict__ ksum) {
    int bn = blockIdx.x;
    int tid = threadIdx.x;
    const float* base = k + (size_t)bn * kBLK * kD + tid;
    float s = 0.f;
#pragma unroll 8
    for (int c = 0; c < kBLK; c++) s += base[(size_t)c * kD];
    ksum[bn * kD + tid] = s;
}

// ---------------- sinkhorn ----------------
__global__ __launch_bounds__(256) void sinkhorn_kernel(const float* __restrict__ ksum,
                                                       const float* __restrict__ sw,
                                                       const int* __restrict__ tokens,
                                                       float* __restrict__ perm_out,
                                                       float* __restrict__ smask_out) {
    int b = blockIdx.x / kH, h = blockIdx.x % kH;
    int tid = threadIdx.x;
    int n = tid >> 4, m = tid & 15;
    const float* kp = ksum + ((size_t)(b * kNB + n)) * kD + h * kDH;
    const float* wp = sw + (size_t)h * kDH * kNB + m;
    float la = 0.f;
#pragma unroll
    for (int d = 0; d < kDH; d++) la += kp[d] * wp[d * kNB];

    __shared__ float sm[16][17];
    for (int it = 0; it < 8; it++) {
        float mx = la;
#pragma unroll
        for (int o = 8; o >= 1; o >>= 1)
            mx = fmaxf(mx, __shfl_xor_sync(0xffffffffu, mx, o, 16));
        float e = expf(la - mx);
        float sum = e;
#pragma unroll
        for (int o = 8; o >= 1; o >>= 1)
            sum += __shfl_xor_sync(0xffffffffu, sum, o, 16);
        la = la - (mx + logf(sum));
        sm[n][m] = la;
        __syncthreads();
        float cmx = -1e30f;
#pragma unroll
        for (int i = 0; i < 16; i++) cmx = fmaxf(cmx, sm[i][m]);
        float cs = 0.f;
#pragma unroll
        for (int i = 0; i < 16; i++) cs += expf(sm[i][m] - cmx);
        la = la - (cmx + logf(cs));
        __syncthreads();
    }
    float p = expf(la);
    sm[n][m] = p;
    perm_out[((size_t)(b * kH + h) * kNB + n) * kNB + m] = p;
    __syncthreads();
    for (int idx = tid; idx < kNB * kBLK; idx += 256) {
        int nn = idx >> 7, c = idx & 127;
        float s = 0.f;
#pragma unroll
        for (int mm = 0; mm < 16; mm++) {
            float mb = (tokens[b * kS + mm * kBLK + c] > 0) ? 1.f : 0.f;
            s += sm[nn][mm] * mb;
        }
        smask_out[((size_t)(b * kH + h) * kNB + nn) * kBLK + c] = (s > 0.5f) ? 1.f : 0.f;
    }
}

// ---------------- sort-mix ----------------
__global__ __launch_bounds__(256) void sortmix_kernel(const float* __restrict__ perm,
                                                      const float* __restrict__ k,
                                                      const float* __restrict__ v,
                                                      float* __restrict__ sk,
                                                      float* __restrict__ sv) {
    int chunk = blockIdx.x;
    int h = blockIdx.y;
    int b = blockIdx.z;
    __shared__ float P[16][16];
    __shared__ float T[16][512];
    int tid = threadIdx.x;
    P[tid >> 4][tid & 15] = perm[(size_t)(b * kH + h) * 256 + tid];
    int cd0 = chunk * 512;

    for (int phase = 0; phase < 2; phase++) {
        const float* src = phase ? v : k;
        float* dst = phase ? sv : sk;
        __syncthreads();
        for (int idx = tid; idx < 16 * 512; idx += 256) {
            int m = idx >> 9;
            int j = idx & 511;
            int cd = cd0 + j;
            int c = cd >> 6, d = cd & 63;
            T[m][j] = src[((size_t)(b * kS + m * kBLK + c)) * kD + h * kDH + d];
        }
        __syncthreads();
        for (int idx = tid; idx < 16 * 512; idx += 256) {
            int n = idx >> 9;
            int j = idx & 511;
            float acc = 0.f;
#pragma unroll
            for (int m = 0; m < 16; m++) acc += P[n][m] * T[m][j];
            int cd = cd0 + j;
            int c = cd >> 6, d = cd & 63;
            dst[((size_t)(b * kS + n * kBLK + c)) * kD + h * kDH + d] = acc;
        }
    }
}

// ---------------- attention ----------------
__global__ __launch_bounds__(128) void attn_kernel(const float* __restrict__ q,
                                                   const float* __restrict__ k,
                                                   const float* __restrict__ v,
                                                   const float* __restrict__ sk,
                                                   const float* __restrict__ sv,
                                                   const float* __restrict__ smask,
                                                   const int* __restrict__ tokens,
                                                   __half* __restrict__ o) {
    int n = blockIdx.x, h = blockIdx.y, b = blockIdx.z;
    int c = threadIdx.x;
    __shared__ float Ks[32][64];
    __shared__ float Vs[32][64];
    __shared__ float biasS[256];
    for (int j = threadIdx.x; j < 256; j += 128) {
        float mv;
        if (j < 128) mv = (tokens[b * kS + n * kBLK + j] > 0) ? 1.f : 0.f;
        else mv = smask[((size_t)(b * kH + h) * kNB + n) * kBLK + (j - 128)];
        biasS[j] = (mv > 0.5f) ? 0.f : -1e9f;
    }
    float qr[64];
    {
        const float4* qp = (const float4*)(q + ((size_t)(b * kS + n * kBLK + c)) * kD + h * kDH);
#pragma unroll
        for (int i = 0; i < 16; i++) {
            float4 t = qp[i];
            qr[4 * i] = t.x; qr[4 * i + 1] = t.y; qr[4 * i + 2] = t.z; qr[4 * i + 3] = t.w;
        }
    }
    float oa[64];
#pragma unroll
    for (int d = 0; d < 64; d++) oa[d] = 0.f;
    float mrun = -1e30f, lrun = 0.f;

    for (int j0 = 0; j0 < 256; j0 += 32) {
        __syncthreads();
        for (int t = threadIdx.x; t < 512; t += 128) {
            int jj = t >> 4;
            int dq = (t & 15) << 2;
            int j = j0 + jj;
            size_t off;
            const float *kb, *vb;
            if (j < 128) {
                off = ((size_t)(b * kS + n * kBLK + j)) * kD + h * kDH + dq;
                kb = k + off; vb = v + off;
            } else {
                off = ((size_t)(b * kS + n * kBLK + (j - 128))) * kD + h * kDH + dq;
                kb = sk + off; vb = sv + off;
            }
            *(float4*)&Ks[jj][dq] = *(const float4*)kb;
            *(float4*)&Vs[jj][dq] = *(const float4*)vb;
        }
        __syncthreads();
        float sreg[32];
        float cmax = -1e30f;
#pragma unroll
        for (int jj = 0; jj < 32; jj++) {
            float s = biasS[j0 + jj];
#pragma unroll
            for (int d = 0; d < 64; d += 4) {
                float4 kv = *(const float4*)&Ks[jj][d];
                s += qr[d] * kv.x + qr[d + 1] * kv.y + qr[d + 2] * kv.z + qr[d + 3] * kv.w;
            }
            sreg[jj] = s;
            cmax = fmaxf(cmax, s);
        }
        float mnew = fmaxf(mrun, cmax);
        float corr = __expf(mrun - mnew);
        lrun *= corr;
#pragma unroll
        for (int d = 0; d < 64; d++) oa[d] *= corr;
#pragma unroll
        for (int jj = 0; jj < 32; jj++) {
            float p = __expf(sreg[jj] - mnew);
            lrun += p;
#pragma unroll
            for (int d = 0; d < 64; d += 4) {
                float4 vv = *(const float4*)&Vs[jj][d];
                oa[d] += p * vv.x; oa[d + 1] += p * vv.y;
                oa[d + 2] += p * vv.z; oa[d + 3] += p * vv.w;
            }
        }
        mrun = mnew;
    }
    float inv = 1.f / lrun;
    __half2* op = (__half2*)(o + ((size_t)(b * kS + n * kBLK + c)) * kD + h * kDH);
#pragma unroll
    for (int d = 0; d < 64; d += 2)
        op[d >> 1] = __floats2half2_rn(oa[d] * inv, oa[d + 1] * inv);
}

// ---------------- host orchestration ----------------
extern "C" void kernel_launch(void* const* d_in, const int* in_sizes, int n_in,
                              void* d_out, int out_size) {
    const int* tokens = (const int*)d_in[0];
    const float* embed = (const float*)d_in[1];
    const float* ln1_s = (const float*)d_in[2];
    const float* ln1_b = (const float*)d_in[3];
    const float* wq = (const float*)d_in[4];
    const float* wk = (const float*)d_in[5];
    const float* wv = (const float*)d_in[6];
    const float* wo = (const float*)d_in[7];
    const float* sortw = (const float*)d_in[8];
    const float* ln2_s = (const float*)d_in[9];
    const float* ln2_b = (const float*)d_in[10];
    const float* w1 = (const float*)d_in[11];
    const float* b1 = (const float*)d_in[12];
    const float* w2 = (const float*)d_in[13];
    const float* b2 = (const float*)d_in[14];
    const float* lnf_s = (const float*)d_in[15];
    const float* lnf_b = (const float*)d_in[16];
    float* out = (float*)d_out;

    float *x, *q, *k, *v, *sk, *sv, *ksum, *perm, *smask;
    __half *hh, *oh, *mlph, *wqh, *wkh, *wvh, *woh, *w1h, *w2h;
    cudaGetSymbolAddress((void**)&x, g_x);
    cudaGetSymbolAddress((void**)&q, g_q);
    cudaGetSymbolAddress((void**)&k, g_k);
    cudaGetSymbolAddress((void**)&v, g_v);
    cudaGetSymbolAddress((void**)&sk, g_sk);
    cudaGetSymbolAddress((void**)&sv, g_sv);
    cudaGetSymbolAddress((void**)&ksum, g_ksum);
    cudaGetSymbolAddress((void**)&perm, g_perm);
    cudaGetSymbolAddress((void**)&smask, g_smask);
    cudaGetSymbolAddress((void**)&hh, g_hh);
    cudaGetSymbolAddress((void**)&oh, g_oh);
    cudaGetSymbolAddress((void**)&mlph, g_mlph);
    cudaGetSymbolAddress((void**)&wqh, g_wq_h);
    cudaGetSymbolAddress((void**)&wkh, g_wk_h);
    cudaGetSymbolAddress((void**)&wvh, g_wv_h);
    cudaGetSymbolAddress((void**)&woh, g_wo_h);
    cudaGetSymbolAddress((void**)&w1h, g_w1_h);
    cudaGetSymbolAddress((void**)&w2h, g_w2_h);

    // weight conversion (once per launch)
    int nW = kL * kD * kD;
    int nM = kL * kD * kMLP;
    f2h_kernel<<<(nW / 4 + 255) / 256, 256>>>(wq, wqh, nW);
    f2h_kernel<<<(nW / 4 + 255) / 256, 256>>>(wk, wkh, nW);
    f2h_kernel<<<(nW / 4 + 255) / 256, 256>>>(wv, wvh, nW);
    f2h_kernel<<<(nW / 4 + 255) / 256, 256>>>(wo, woh, nW);
    f2h_kernel<<<(nM / 4 + 255) / 256, 256>>>(w1, w1h, nM);
    f2h_kernel<<<(nM / 4 + 255) / 256, 256>>>(w2, w2h, nM);

    embed_pe_kernel<<<(kBSD + 255) / 256, 256>>>(tokens, embed, x);

    const float qscale = 1.0f / 8.0f;
    dim3 gD(kD / 128, kBS / 128);
    dim3 gM(kMLP / 128, kBS / 128);

    for (int l = 0; l < kL; l++) {
        __half* wq_l = wqh + (size_t)l * kD * kD;
        __half* wk_l = wkh + (size_t)l * kD * kD;
        __half* wv_l = wvh + (size_t)l * kD * kD;
        __half* wo_l = woh + (size_t)l * kD * kD;
        const float* sw_l = sortw + (size_t)l * kH * kDH * kNB;
        __half* w1_l = w1h + (size_t)l * kD * kMLP;
        const float* b1_l = b1 + (size_t)l * kMLP;
        __half* w2_l = w2h + (size_t)l * kMLP * kD;
        const float* b2_l = b2 + (size_t)l * kD;

        ln_kernel<<<kBS, 128>>>(x, ln1_s + l * kD, ln1_b + l * kD, hh, nullptr);
        hgemm_kernel<<<gD, 256>>>(kBS, kD, kD, qscale, hh, wq_l, nullptr, nullptr, q, nullptr, 0);
        hgemm_kernel<<<gD, 256>>>(kBS, kD, kD, 1.0f, hh, wk_l, nullptr, nullptr, k, nullptr, 0);
        hgemm_kernel<<<gD, 256>>>(kBS, kD, kD, 1.0f, hh, wv_l, nullptr, nullptr, v, nullptr, 0);

        ksum_kernel<<<kB * kNB, 512>>>(k, ksum);
        sinkhorn_kernel<<<kB * kH, 256>>>(ksum, sw_l, tokens, perm, smask);
        sortmix_kernel<<<dim3(16, kH, kB), 256>>>(perm, k, v, sk, sv);

        attn_kernel<<<dim3(kNB, kH, kB), 128>>>(q, k, v, sk, sv, smask, tokens, oh);

        // x = x + o @ wo
        hgemm_kernel<<<gD, 256>>>(kBS, kD, kD, 1.0f, oh, wo_l, nullptr, x, x, nullptr, 2);

        // MLP
        ln_kernel<<<kBS, 128>>>(x, ln2_s + l * kD, ln2_b + l * kD, hh, nullptr);
        hgemm_kernel<<<gM, 256>>>(kBS, kMLP, kD, 1.0f, hh, w1_l, b1_l, nullptr, nullptr, mlph, 1);
        hgemm_kernel<<<gD, 256>>>(kBS, kD, kMLP, 1.0f, mlph, w2_l, b2_l, x, x, nullptr, 2);
    }

    ln_kernel<<<kBS, 128>>>(x, lnf_s, lnf_b, nullptr, out);
}

// round 6
// speedup vs baseline: 3.2778x; 1.0275x over previous
#include <cuda_runtime.h>
#include <cuda_fp16.h>
#include <math.h>
#include <stdint.h>

// ---------------- problem dims ----------------
constexpr int kB = 4, kS = 2048, kD = 512, kH = 8, kDH = 64;
constexpr int kMLP = 2048, kBLK = 128, kNB = 16, kL = 4;
constexpr int kBS = kB * kS;                 // 8192 rows
constexpr int kBSD = kBS * kD;               // 4,194,304

// ---------------- scratch (static device globals; no allocation) ----------------
static __device__ float g_x[kBSD];
static __device__ float g_q[kBSD];
static __device__ float g_k[kBSD];
static __device__ float g_v[kBSD];
static __device__ float g_sk[kBSD];
static __device__ float g_sv[kBSD];
static __device__ __align__(256) __half g_hh[kBSD];          // LN outputs (fp16)
static __device__ __align__(256) __half g_oh[kBSD];          // attention out (fp16)
static __device__ __align__(256) __half g_mlph[kBS * kMLP];  // gelu out (fp16)
static __device__ __align__(256) __half g_wq_h[kL * kD * kD];
static __device__ __align__(256) __half g_wk_h[kL * kD * kD];
static __device__ __align__(256) __half g_wv_h[kL * kD * kD];
static __device__ __align__(256) __half g_wo_h[kL * kD * kD];
static __device__ __align__(256) __half g_w1_h[kL * kD * kMLP];
static __device__ __align__(256) __half g_w2_h[kL * kMLP * kD];
static __device__ float g_ksum[kB * kNB * kD];
static __device__ float g_perm[kB * kH * kNB * kNB];
static __device__ float g_smask[kB * kH * kNB * kBLK];

// ---------------- fp32 -> fp16 bulk convert (all 6 weights, 1 launch) ----------------
__global__ void f2h6_kernel(const float* __restrict__ s0, const float* __restrict__ s1,
                            const float* __restrict__ s2, const float* __restrict__ s3,
                            const float* __restrict__ s4, const float* __restrict__ s5,
                            __half* __restrict__ d0, __half* __restrict__ d1,
                            __half* __restrict__ d2, __half* __restrict__ d3,
                            __half* __restrict__ d4, __half* __restrict__ d5,
                            int nW, int nM) {
    int seg = blockIdx.y;
    int n = (seg < 4) ? nW : nM;
    int i = (blockIdx.x * 256 + threadIdx.x) * 4;
    if (i >= n) return;
    const float* s; __half* d;
    switch (seg) {
        case 0: s = s0; d = d0; break;
        case 1: s = s1; d = d1; break;
        case 2: s = s2; d = d2; break;
        case 3: s = s3; d = d3; break;
        case 4: s = s4; d = d4; break;
        default: s = s5; d = d5; break;
    }
    float4 f = *(const float4*)(s + i);
    __half2* dp = (__half2*)(d + i);
    dp[0] = __floats2half2_rn(f.x, f.y);
    dp[1] = __floats2half2_rn(f.z, f.w);
}

// ---------------- embed + positional encoding ----------------
__global__ void embed_pe_kernel(const int* __restrict__ tokens,
                                const float* __restrict__ embed,
                                float* __restrict__ x) {
    int idx = blockIdx.x * 256 + threadIdx.x;
    if (idx >= kBSD) return;
    int d = idx & (kD - 1);
    int bs = idx >> 9;
    int s = bs & (kS - 1);
    int tok = tokens[bs];
    int i2 = (d >> 1) * 2;
    float freq = expf(-(float)i2 * (logf(10000.0f) / (float)kD));
    float ang = (float)s * freq;
    float pe = (d & 1) ? cosf(ang) : sinf(ang);
    x[idx] = embed[tok * kD + d] + pe;
}

// ---------------- layernorm: fp32 in, fp16 out (or fp32 for final) ----------------
__global__ __launch_bounds__(128) void ln_kernel(const float* __restrict__ x,
                                                 const float* __restrict__ sc,
                                                 const float* __restrict__ bi,
                                                 __half* __restrict__ outh,
                                                 float* __restrict__ outf) {
    int row = blockIdx.x;
    const float* xp = x + (size_t)row * kD;
    float v[4];
    float s = 0.f, ss = 0.f;
#pragma unroll
    for (int i = 0; i < 4; i++) {
        v[i] = xp[threadIdx.x + i * 128];
        s += v[i];
        ss += v[i] * v[i];
    }
#pragma unroll
    for (int o = 16; o >= 1; o >>= 1) {
        s += __shfl_down_sync(0xffffffffu, s, o);
        ss += __shfl_down_sync(0xffffffffu, ss, o);
    }
    __shared__ float sa[4], sb[4];
    int w = threadIdx.x >> 5;
    if ((threadIdx.x & 31) == 0) { sa[w] = s; sb[w] = ss; }
    __syncthreads();
    s = sa[0] + sa[1] + sa[2] + sa[3];
    ss = sb[0] + sb[1] + sb[2] + sb[3];
    float mean = s * (1.0f / kD);
    float var = ss * (1.0f / kD) - mean * mean;
    float r = rsqrtf(var + 1e-6f);
#pragma unroll
    for (int i = 0; i < 4; i++) {
        int d = threadIdx.x + i * 128;
        float o = (v[i] - mean) * r * sc[d] + bi[d];
        if (outh) outh[(size_t)row * kD + d] = __float2half_rn(o);
        else outf[(size_t)row * kD + d] = o;
    }
}

// ---------------- fp16 tensor-core GEMM (4-stage cp.async pipeline) ----------------
__device__ __forceinline__ float gelu_f(float x) {
    const float c = 0.7978845608028654f;
    float x3 = x * x * x;
    return 0.5f * x * (1.0f + tanhf(c * (x + 0.044715f * x3)));
}

__device__ __forceinline__ uint32_t smem_u32(const void* p) {
    return (uint32_t)__cvta_generic_to_shared(p);
}
__device__ __forceinline__ void ldsm_x4(uint32_t& r0, uint32_t& r1, uint32_t& r2,
                                        uint32_t& r3, uint32_t addr) {
    asm volatile("ldmatrix.sync.aligned.m8n8.x4.shared.b16 {%0,%1,%2,%3},[%4];"
                 : "=r"(r0), "=r"(r1), "=r"(r2), "=r"(r3) : "r"(addr));
}
__device__ __forceinline__ void ldsm_x4t(uint32_t& r0, uint32_t& r1, uint32_t& r2,
                                         uint32_t& r3, uint32_t addr) {
    asm volatile("ldmatrix.sync.aligned.m8n8.x4.trans.shared.b16 {%0,%1,%2,%3},[%4];"
                 : "=r"(r0), "=r"(r1), "=r"(r2), "=r"(r3) : "r"(addr));
}
__device__ __forceinline__ void mma_f16(float* c, uint32_t a0, uint32_t a1,
                                        uint32_t a2, uint32_t a3,
                                        uint32_t b0, uint32_t b1) {
    asm volatile(
        "mma.sync.aligned.m16n8k16.row.col.f32.f16.f16.f32 "
        "{%0,%1,%2,%3},{%4,%5,%6,%7},{%8,%9},{%0,%1,%2,%3};"
        : "+f"(c[0]), "+f"(c[1]), "+f"(c[2]), "+f"(c[3])
        : "r"(a0), "r"(a1), "r"(a2), "r"(a3), "r"(b0), "r"(b1));
}
__device__ __forceinline__ void cp16(uint32_t dst, const void* src) {
    asm volatile("cp.async.cg.shared.global [%0],[%1],16;" :: "r"(dst), "l"(src));
}

constexpr int kStages = 4;
constexpr int kBM = 128, kBN = 128, kBKg = 32;
constexpr int kAP = 40, kBP = 136;                  // pitches in halves
constexpr int kASTG = kBM * kAP;                    // halves per A stage
constexpr int kBSTG = kBKg * kBP;                   // halves per B stage
constexpr int kSmemHalves = kStages * (kASTG + kBSTG);
constexpr int kSmemBytes = kSmemHalves * 2;         // 75776

// epi 0: Cf = alpha*acc
// epi 1: Ch = gelu(acc + bias)
// epi 2: Cf = resid + acc + (bias? bias : 0)
__global__ __launch_bounds__(256, 2) void hgemm_kernel(
    int M, int N, int K, float alpha,
    const __half* __restrict__ A, const __half* __restrict__ Bm,
    const float* __restrict__ bias, const float* __restrict__ resid,
    float* __restrict__ Cf, __half* __restrict__ Ch, int epi) {
    extern __shared__ __half smem[];
    __half* As = smem;                       // [kStages][kASTG]
    __half* Bs = smem + kStages * kASTG;     // [kStages][kBSTG]

    int tid = threadIdx.x, lane = tid & 31, w = tid >> 5;
    int wr = w >> 2, wc = w & 3;             // 2x4 warp grid, warp tile 64x32
    int br = blockIdx.y, bc = blockIdx.x;
    const __half* Ap = A + (size_t)br * kBM * K;
    const __half* Bp = Bm + (size_t)bc * kBN;

    float acc[4][4][4];
#pragma unroll
    for (int i = 0; i < 4; i++)
#pragma unroll
        for (int j = 0; j < 4; j++)
#pragma unroll
            for (int r = 0; r < 4; r++) acc[i][j][r] = 0.f;

    int arow = tid >> 2, achk = tid & 3;
    int brow = tid >> 4, bchk = tid & 15;

    auto issue = [&](int stage, int k0) {
        uint32_t ab = smem_u32(As + stage * kASTG);
        uint32_t bb = smem_u32(Bs + stage * kBSTG);
#pragma unroll
        for (int p = 0; p < 2; p++) {
            int r = arow + p * 64;
            cp16(ab + (uint32_t)(r * kAP + achk * 8) * 2, Ap + (size_t)r * K + k0 + achk * 8);
        }
#pragma unroll
        for (int p = 0; p < 2; p++) {
            int r = brow + p * 16;
            cp16(bb + (uint32_t)(r * kBP + bchk * 8) * 2, Bp + (size_t)(k0 + r) * N + bchk * 8);
        }
        asm volatile("cp.async.commit_group;");
    };

    int nt = K / kBKg;
    // prologue: issue stages-1 tiles
#pragma unroll
    for (int t = 0; t < kStages - 1; t++) issue(t, t * kBKg);

    int rowoff = (lane & 7) + ((lane >> 3) & 1) * 8;
    int seloff = (lane >> 4) * 8;

    for (int t = 0; t < nt; t++) {
        asm volatile("cp.async.wait_group %0;" :: "n"(kStages - 2));
        __syncthreads();
        int tn = t + kStages - 1;
        if (tn < nt) issue(tn % kStages, tn * kBKg);
        int buf = t % kStages;
        const __half* Ab = As + buf * kASTG;
        const __half* Bb = Bs + buf * kBSTG;
#pragma unroll
        for (int s = 0; s < 2; s++) {
            int k0 = s * 16;
            uint32_t af[4][4], bf[4][2];
#pragma unroll
            for (int i = 0; i < 4; i++) {
                int m0 = wr * 64 + i * 16;
                uint32_t addr = smem_u32(Ab + (m0 + rowoff) * kAP + k0 + seloff);
                ldsm_x4(af[i][0], af[i][1], af[i][2], af[i][3], addr);
            }
#pragma unroll
            for (int j2 = 0; j2 < 2; j2++) {
                int n0 = wc * 32 + j2 * 16;
                uint32_t addr = smem_u32(Bb + (k0 + rowoff) * kBP + n0 + seloff);
                uint32_t r0, r1, r2, r3;
                ldsm_x4t(r0, r1, r2, r3, addr);
                bf[j2 * 2][0] = r0; bf[j2 * 2][1] = r1;
                bf[j2 * 2 + 1][0] = r2; bf[j2 * 2 + 1][1] = r3;
            }
#pragma unroll
            for (int i = 0; i < 4; i++)
#pragma unroll
                for (int j = 0; j < 4; j++)
                    mma_f16(acc[i][j], af[i][0], af[i][1], af[i][2], af[i][3],
                            bf[j][0], bf[j][1]);
        }
    }

    int lq = lane >> 2, lr = lane & 3;
#pragma unroll
    for (int i = 0; i < 4; i++) {
        int r0 = br * kBM + wr * 64 + i * 16 + lq;
#pragma unroll
        for (int j = 0; j < 4; j++) {
            int col = bc * kBN + wc * 32 + j * 8 + lr * 2;
#pragma unroll
            for (int half = 0; half < 2; half++) {
                int row = r0 + half * 8;
                float v0 = acc[i][j][half * 2 + 0];
                float v1 = acc[i][j][half * 2 + 1];
                if (epi == 0) {
                    v0 *= alpha; v1 *= alpha;
                    *(float2*)(Cf + (size_t)row * N + col) = make_float2(v0, v1);
                } else if (epi == 1) {
                    v0 = gelu_f(v0 + bias[col]);
                    v1 = gelu_f(v1 + bias[col + 1]);
                    *(__half2*)(Ch + (size_t)row * N + col) = __floats2half2_rn(v0, v1);
                } else {
                    const float* rp = resid + (size_t)row * N + col;
                    float2 rr = *(const float2*)rp;
                    v0 += rr.x; v1 += rr.y;
                    if (bias) { v0 += bias[col]; v1 += bias[col + 1]; }
                    *(float2*)(Cf + (size_t)row * N + col) = make_float2(v0, v1);
                }
            }
        }
    }
}

// ---------------- ksum ----------------
__global__ __launch_bounds__(512) void ksum_kernel(const float* __restrict__ k,
                                                   float* __restrict__ ksum) {
    int bn = blockIdx.x;
    int tid = threadIdx.x;
    const float* base = k + (size_t)bn * kBLK * kD + tid;
    float s = 0.f;
#pragma unroll 8
    for (int c = 0; c < kBLK; c++) s += base[(size_t)c * kD];
    ksum[bn * kD + tid] = s;
}

// ---------------- sinkhorn ----------------
__global__ __launch_bounds__(256) void sinkhorn_kernel(const float* __restrict__ ksum,
                                                       const float* __restrict__ sw,
                                                       const int* __restrict__ tokens,
                                                       float* __restrict__ perm_out,
                                                       float* __restrict__ smask_out) {
    int b = blockIdx.x / kH, h = blockIdx.x % kH;
    int tid = threadIdx.x;
    int n = tid >> 4, m = tid & 15;
    const float* kp = ksum + ((size_t)(b * kNB + n)) * kD + h * kDH;
    const float* wp = sw + (size_t)h * kDH * kNB + m;
    float la = 0.f;
#pragma unroll
    for (int d = 0; d < kDH; d++) la += kp[d] * wp[d * kNB];

    __shared__ float sm[16][17];
    for (int it = 0; it < 8; it++) {
        float mx = la;
#pragma unroll
        for (int o = 8; o >= 1; o >>= 1)
            mx = fmaxf(mx, __shfl_xor_sync(0xffffffffu, mx, o, 16));
        float e = expf(la - mx);
        float sum = e;
#pragma unroll
        for (int o = 8; o >= 1; o >>= 1)
            sum += __shfl_xor_sync(0xffffffffu, sum, o, 16);
        la = la - (mx + logf(sum));
        sm[n][m] = la;
        __syncthreads();
        float cmx = -1e30f;
#pragma unroll
        for (int i = 0; i < 16; i++) cmx = fmaxf(cmx, sm[i][m]);
        float cs = 0.f;
#pragma unroll
        for (int i = 0; i < 16; i++) cs += expf(sm[i][m] - cmx);
        la = la - (cmx + logf(cs));
        __syncthreads();
    }
    float p = expf(la);
    sm[n][m] = p;
    perm_out[((size_t)(b * kH + h) * kNB + n) * kNB + m] = p;
    __syncthreads();
    for (int idx = tid; idx < kNB * kBLK; idx += 256) {
        int nn = idx >> 7, c = idx & 127;
        float s = 0.f;
#pragma unroll
        for (int mm = 0; mm < 16; mm++) {
            float mb = (tokens[b * kS + mm * kBLK + c] > 0) ? 1.f : 0.f;
            s += sm[nn][mm] * mb;
        }
        smask_out[((size_t)(b * kH + h) * kNB + nn) * kBLK + c] = (s > 0.5f) ? 1.f : 0.f;
    }
}

// ---------------- sort-mix ----------------
__global__ __launch_bounds__(256) void sortmix_kernel(const float* __restrict__ perm,
                                                      const float* __restrict__ k,
                                                      const float* __restrict__ v,
                                                      float* __restrict__ sk,
                                                      float* __restrict__ sv) {
    int chunk = blockIdx.x;
    int h = blockIdx.y;
    int b = blockIdx.z;
    __shared__ float P[16][16];
    __shared__ float T[16][512];
    int tid = threadIdx.x;
    P[tid >> 4][tid & 15] = perm[(size_t)(b * kH + h) * 256 + tid];
    int cd0 = chunk * 512;

    for (int phase = 0; phase < 2; phase++) {
        const float* src = phase ? v : k;
        float* dst = phase ? sv : sk;
        __syncthreads();
        for (int idx = tid; idx < 16 * 512; idx += 256) {
            int m = idx >> 9;
            int j = idx & 511;
            int cd = cd0 + j;
            int c = cd >> 6, d = cd & 63;
            T[m][j] = src[((size_t)(b * kS + m * kBLK + c)) * kD + h * kDH + d];
        }
        __syncthreads();
        for (int idx = tid; idx < 16 * 512; idx += 256) {
            int n = idx >> 9;
            int j = idx & 511;
            float acc = 0.f;
#pragma unroll
            for (int m = 0; m < 16; m++) acc += P[n][m] * T[m][j];
            int cd = cd0 + j;
            int c = cd >> 6, d = cd & 63;
            dst[((size_t)(b * kS + n * kBLK + c)) * kD + h * kDH + d] = acc;
        }
    }
}

// ---------------- attention ----------------
__global__ __launch_bounds__(128) void attn_kernel(const float* __restrict__ q,
                                                   const float* __restrict__ k,
                                                   const float* __restrict__ v,
                                                   const float* __restrict__ sk,
                                                   const float* __restrict__ sv,
                                                   const float* __restrict__ smask,
                                                   const int* __restrict__ tokens,
                                                   __half* __restrict__ o) {
    int n = blockIdx.x, h = blockIdx.y, b = blockIdx.z;
    int c = threadIdx.x;
    __shared__ float Ks[32][64];
    __shared__ float Vs[32][64];
    __shared__ float biasS[256];
    for (int j = threadIdx.x; j < 256; j += 128) {
        float mv;
        if (j < 128) mv = (tokens[b * kS + n * kBLK + j] > 0) ? 1.f : 0.f;
        else mv = smask[((size_t)(b * kH + h) * kNB + n) * kBLK + (j - 128)];
        biasS[j] = (mv > 0.5f) ? 0.f : -1e9f;
    }
    float qr[64];
    {
        const float4* qp = (const float4*)(q + ((size_t)(b * kS + n * kBLK + c)) * kD + h * kDH);
#pragma unroll
        for (int i = 0; i < 16; i++) {
            float4 t = qp[i];
            qr[4 * i] = t.x; qr[4 * i + 1] = t.y; qr[4 * i + 2] = t.z; qr[4 * i + 3] = t.w;
        }
    }
    float oa[64];
#pragma unroll
    for (int d = 0; d < 64; d++) oa[d] = 0.f;
    float mrun = -1e30f, lrun = 0.f;

    for (int j0 = 0; j0 < 256; j0 += 32) {
        __syncthreads();
        for (int t = threadIdx.x; t < 512; t += 128) {
            int jj = t >> 4;
            int dq = (t & 15) << 2;
            int j = j0 + jj;
            size_t off;
            const float *kb, *vb;
            if (j < 128) {
                off = ((size_t)(b * kS + n * kBLK + j)) * kD + h * kDH + dq;
                kb = k + off; vb = v + off;
            } else {
                off = ((size_t)(b * kS + n * kBLK + (j - 128))) * kD + h * kDH + dq;
                kb = sk + off; vb = sv + off;
            }
            *(float4*)&Ks[jj][dq] = *(const float4*)kb;
            *(float4*)&Vs[jj][dq] = *(const float4*)vb;
        }
        __syncthreads();
        float sreg[32];
        float cmax = -1e30f;
#pragma unroll
        for (int jj = 0; jj < 32; jj++) {
            float s = biasS[j0 + jj];
#pragma unroll
            for (int d = 0; d < 64; d += 4) {
                float4 kv = *(const float4*)&Ks[jj][d];
                s += qr[d] * kv.x + qr[d + 1] * kv.y + qr[d + 2] * kv.z + qr[d + 3] * kv.w;
            }
            sreg[jj] = s;
            cmax = fmaxf(cmax, s);
        }
        float mnew = fmaxf(mrun, cmax);
        float corr = __expf(mrun - mnew);
        lrun *= corr;
#pragma unroll
        for (int d = 0; d < 64; d++) oa[d] *= corr;
#pragma unroll
        for (int jj = 0; jj < 32; jj++) {
            float p = __expf(sreg[jj] - mnew);
            lrun += p;
#pragma unroll
            for (int d = 0; d < 64; d += 4) {
                float4 vv = *(const float4*)&Vs[jj][d];
                oa[d] += p * vv.x; oa[d + 1] += p * vv.y;
                oa[d + 2] += p * vv.z; oa[d + 3] += p * vv.w;
            }
        }
        mrun = mnew;
    }
    float inv = 1.f / lrun;
    __half2* op = (__half2*)(o + ((size_t)(b * kS + n * kBLK + c)) * kD + h * kDH);
#pragma unroll
    for (int d = 0; d < 64; d += 2)
        op[d >> 1] = __floats2half2_rn(oa[d] * inv, oa[d + 1] * inv);
}

// ---------------- host orchestration ----------------
extern "C" void kernel_launch(void* const* d_in, const int* in_sizes, int n_in,
                              void* d_out, int out_size) {
    const int* tokens = (const int*)d_in[0];
    const float* embed = (const float*)d_in[1];
    const float* ln1_s = (const float*)d_in[2];
    const float* ln1_b = (const float*)d_in[3];
    const float* wq = (const float*)d_in[4];
    const float* wk = (const float*)d_in[5];
    const float* wv = (const float*)d_in[6];
    const float* wo = (const float*)d_in[7];
    const float* sortw = (const float*)d_in[8];
    const float* ln2_s = (const float*)d_in[9];
    const float* ln2_b = (const float*)d_in[10];
    const float* w1 = (const float*)d_in[11];
    const float* b1 = (const float*)d_in[12];
    const float* w2 = (const float*)d_in[13];
    const float* b2 = (const float*)d_in[14];
    const float* lnf_s = (const float*)d_in[15];
    const float* lnf_b = (const float*)d_in[16];
    float* out = (float*)d_out;

    float *x, *q, *k, *v, *sk, *sv, *ksum, *perm, *smask;
    __half *hh, *oh, *mlph, *wqh, *wkh, *wvh, *woh, *w1h, *w2h;
    cudaGetSymbolAddress((void**)&x, g_x);
    cudaGetSymbolAddress((void**)&q, g_q);
    cudaGetSymbolAddress((void**)&k, g_k);
    cudaGetSymbolAddress((void**)&v, g_v);
    cudaGetSymbolAddress((void**)&sk, g_sk);
    cudaGetSymbolAddress((void**)&sv, g_sv);
    cudaGetSymbolAddress((void**)&ksum, g_ksum);
    cudaGetSymbolAddress((void**)&perm, g_perm);
    cudaGetSymbolAddress((void**)&smask, g_smask);
    cudaGetSymbolAddress((void**)&hh, g_hh);
    cudaGetSymbolAddress((void**)&oh, g_oh);
    cudaGetSymbolAddress((void**)&mlph, g_mlph);
    cudaGetSymbolAddress((void**)&wqh, g_wq_h);
    cudaGetSymbolAddress((void**)&wkh, g_wk_h);
    cudaGetSymbolAddress((void**)&wvh, g_wv_h);
    cudaGetSymbolAddress((void**)&woh, g_wo_h);
    cudaGetSymbolAddress((void**)&w1h, g_w1_h);
    cudaGetSymbolAddress((void**)&w2h, g_w2_h);

    cudaFuncSetAttribute(hgemm_kernel, cudaFuncAttributeMaxDynamicSharedMemorySize,
                         kSmemBytes);

    // weight conversion (one launch)
    int nW = kL * kD * kD;
    int nM = kL * kD * kMLP;
    {
        dim3 g(nM / 4 / 256, 6);
        f2h6_kernel<<<g, 256>>>(wq, wk, wv, wo, w1, w2,
                                wqh, wkh, wvh, woh, w1h, w2h, nW, nM);
    }

    embed_pe_kernel<<<(kBSD + 255) / 256, 256>>>(tokens, embed, x);

    const float qscale = 1.0f / 8.0f;
    dim3 gD(kD / 128, kBS / 128);
    dim3 gM(kMLP / 128, kBS / 128);

    for (int l = 0; l < kL; l++) {
        __half* wq_l = wqh + (size_t)l * kD * kD;
        __half* wk_l = wkh + (size_t)l * kD * kD;
        __half* wv_l = wvh + (size_t)l * kD * kD;
        __half* wo_l = woh + (size_t)l * kD * kD;
        const float* sw_l = sortw + (size_t)l * kH * kDH * kNB;
        __half* w1_l = w1h + (size_t)l * kD * kMLP;
        const float* b1_l = b1 + (size_t)l * kMLP;
        __half* w2_l = w2h + (size_t)l * kMLP * kD;
        const float* b2_l = b2 + (size_t)l * kD;

        ln_kernel<<<kBS, 128>>>(x, ln1_s + l * kD, ln1_b + l * kD, hh, nullptr);
        hgemm_kernel<<<gD, 256, kSmemBytes>>>(kBS, kD, kD, qscale, hh, wq_l, nullptr, nullptr, q, nullptr, 0);
        hgemm_kernel<<<gD, 256, kSmemBytes>>>(kBS, kD, kD, 1.0f, hh, wk_l, nullptr, nullptr, k, nullptr, 0);
        hgemm_kernel<<<gD, 256, kSmemBytes>>>(kBS, kD, kD, 1.0f, hh, wv_l, nullptr, nullptr, v, nullptr, 0);

        ksum_kernel<<<kB * kNB, 512>>>(k, ksum);
        sinkhorn_kernel<<<kB * kH, 256>>>(ksum, sw_l, tokens, perm, smask);
        sortmix_kernel<<<dim3(16, kH, kB), 256>>>(perm, k, v, sk, sv);

        attn_kernel<<<dim3(kNB, kH, kB), 128>>>(q, k, v, sk, sv, smask, tokens, oh);

        // x = x + o @ wo
        hgemm_kernel<<<gD, 256, kSmemBytes>>>(kBS, kD, kD, 1.0f, oh, wo_l, nullptr, x, x, nullptr, 2);

        // MLP
        ln_kernel<<<kBS, 128>>>(x, ln2_s + l * kD, ln2_b + l * kD, hh, nullptr);
        hgemm_kernel<<<gM, 256, kSmemBytes>>>(kBS, kMLP, kD, 1.0f, hh, w1_l, b1_l, nullptr, nullptr, mlph, 1);
        hgemm_kernel<<<gD, 256, kSmemBytes>>>(kBS, kD, kMLP, 1.0f, mlph, w2_l, b2_l, x, x, nullptr, 2);
    }

    ln_kernel<<<kBS, 128>>>(x, lnf_s, lnf_b, nullptr, out);
}

// round 8
// speedup vs baseline: 5.1920x; 1.5840x over previous
#include <cuda_runtime.h>
#include <cuda_fp16.h>
#include <math.h>
#include <stdint.h>

// ---------------- problem dims ----------------
constexpr int kB = 4, kS = 2048, kD = 512, kH = 8, kDH = 64;
constexpr int kMLP = 2048, kBLK = 128, kNB = 16, kL = 4;
constexpr int kBS = kB * kS;                 // 8192 rows
constexpr int kBSD = kBS * kD;               // 4,194,304

// ---------------- scratch (static device globals; no allocation) ----------------
static __device__ float g_x[kBSD];
static __device__ __align__(256) __half g_qh[kBSD];
static __device__ __align__(256) __half g_kh[kBSD];
static __device__ __align__(256) __half g_vh[kBSD];
static __device__ __align__(256) __half g_skh[kBSD];
static __device__ __align__(256) __half g_svh[kBSD];
static __device__ __align__(256) __half g_hh[kBSD];          // LN outputs (fp16)
static __device__ __align__(256) __half g_oh[kBSD];          // attention out (fp16)
static __device__ __align__(256) __half g_mlph[kBS * kMLP];  // gelu out (fp16)
static __device__ __align__(256) __half g_wq_h[kL * kD * kD];
static __device__ __align__(256) __half g_wk_h[kL * kD * kD];
static __device__ __align__(256) __half g_wv_h[kL * kD * kD];
static __device__ __align__(256) __half g_wo_h[kL * kD * kD];
static __device__ __align__(256) __half g_w1_h[kL * kD * kMLP];
static __device__ __align__(256) __half g_w2_h[kL * kMLP * kD];
static __device__ float g_ksum[kB * kNB * kD];
static __device__ float g_perm[kB * kH * kNB * kNB];
static __device__ float g_smask[kB * kH * kNB * kBLK];

// ---------------- fp32 -> fp16 bulk convert (all 6 weights, 1 launch) ----------------
__global__ void f2h6_kernel(const float* __restrict__ s0, const float* __restrict__ s1,
                            const float* __restrict__ s2, const float* __restrict__ s3,
                            const float* __restrict__ s4, const float* __restrict__ s5,
                            __half* __restrict__ d0, __half* __restrict__ d1,
                            __half* __restrict__ d2, __half* __restrict__ d3,
                            __half* __restrict__ d4, __half* __restrict__ d5,
                            int nW, int nM) {
    int seg = blockIdx.y;
    int n = (seg < 4) ? nW : nM;
    int i = (blockIdx.x * 256 + threadIdx.x) * 4;
    if (i >= n) return;
    const float* s; __half* d;
    switch (seg) {
        case 0: s = s0; d = d0; break;
        case 1: s = s1; d = d1; break;
        case 2: s = s2; d = d2; break;
        case 3: s = s3; d = d3; break;
        case 4: s = s4; d = d4; break;
        default: s = s5; d = d5; break;
    }
    float4 f = *(const float4*)(s + i);
    __half2* dp = (__half2*)(d + i);
    dp[0] = __floats2half2_rn(f.x, f.y);
    dp[1] = __floats2half2_rn(f.z, f.w);
}

// ---------------- embed + positional encoding ----------------
__global__ void embed_pe_kernel(const int* __restrict__ tokens,
                                const float* __restrict__ embed,
                                float* __restrict__ x) {
    int idx = blockIdx.x * 256 + threadIdx.x;
    if (idx >= kBSD) return;
    int d = idx & (kD - 1);
    int bs = idx >> 9;
    int s = bs & (kS - 1);
    int tok = tokens[bs];
    int i2 = (d >> 1) * 2;
    float freq = expf(-(float)i2 * (logf(10000.0f) / (float)kD));
    float ang = (float)s * freq;
    float pe = (d & 1) ? cosf(ang) : sinf(ang);
    x[idx] = embed[tok * kD + d] + pe;
}

// ---------------- layernorm: fp32 in, fp16 out (or fp32 for final) ----------------
__global__ __launch_bounds__(128) void ln_kernel(const float* __restrict__ x,
                                                 const float* __restrict__ sc,
                                                 const float* __restrict__ bi,
                                                 __half* __restrict__ outh,
                                                 float* __restrict__ outf) {
    int row = blockIdx.x;
    const float* xp = x + (size_t)row * kD;
    float v[4];
    float s = 0.f, ss = 0.f;
#pragma unroll
    for (int i = 0; i < 4; i++) {
        v[i] = xp[threadIdx.x + i * 128];
        s += v[i];
        ss += v[i] * v[i];
    }
#pragma unroll
    for (int o = 16; o >= 1; o >>= 1) {
        s += __shfl_down_sync(0xffffffffu, s, o);
        ss += __shfl_down_sync(0xffffffffu, ss, o);
    }
    __shared__ float sa[4], sb[4];
    int w = threadIdx.x >> 5;
    if ((threadIdx.x & 31) == 0) { sa[w] = s; sb[w] = ss; }
    __syncthreads();
    s = sa[0] + sa[1] + sa[2] + sa[3];
    ss = sb[0] + sb[1] + sb[2] + sb[3];
    float mean = s * (1.0f / kD);
    float var = ss * (1.0f / kD) - mean * mean;
    float r = rsqrtf(var + 1e-6f);
#pragma unroll
    for (int i = 0; i < 4; i++) {
        int d = threadIdx.x + i * 128;
        float o = (v[i] - mean) * r * sc[d] + bi[d];
        if (outh) outh[(size_t)row * kD + d] = __float2half_rn(o);
        else outf[(size_t)row * kD + d] = o;
    }
}

// ---------------- mma helpers ----------------
__device__ __forceinline__ float gelu_f(float x) {
    const float c = 0.7978845608028654f;
    float x3 = x * x * x;
    return 0.5f * x * (1.0f + tanhf(c * (x + 0.044715f * x3)));
}
__device__ __forceinline__ uint32_t smem_u32(const void* p) {
    return (uint32_t)__cvta_generic_to_shared(p);
}
__device__ __forceinline__ void ldsm_x4(uint32_t& r0, uint32_t& r1, uint32_t& r2,
                                        uint32_t& r3, uint32_t addr) {
    asm volatile("ldmatrix.sync.aligned.m8n8.x4.shared.b16 {%0,%1,%2,%3},[%4];"
                 : "=r"(r0), "=r"(r1), "=r"(r2), "=r"(r3) : "r"(addr));
}
__device__ __forceinline__ void ldsm_x4t(uint32_t& r0, uint32_t& r1, uint32_t& r2,
                                         uint32_t& r3, uint32_t addr) {
    asm volatile("ldmatrix.sync.aligned.m8n8.x4.trans.shared.b16 {%0,%1,%2,%3},[%4];"
                 : "=r"(r0), "=r"(r1), "=r"(r2), "=r"(r3) : "r"(addr));
}
__device__ __forceinline__ void mma_f16(float* c, uint32_t a0, uint32_t a1,
                                        uint32_t a2, uint32_t a3,
                                        uint32_t b0, uint32_t b1) {
    asm volatile(
        "mma.sync.aligned.m16n8k16.row.col.f32.f16.f16.f32 "
        "{%0,%1,%2,%3},{%4,%5,%6,%7},{%8,%9},{%0,%1,%2,%3};"
        : "+f"(c[0]), "+f"(c[1]), "+f"(c[2]), "+f"(c[3])
        : "r"(a0), "r"(a1), "r"(a2), "r"(a3), "r"(b0), "r"(b1));
}
__device__ __forceinline__ void cp16(uint32_t dst, const void* src) {
    asm volatile("cp.async.cg.shared.global [%0],[%1],16;" :: "r"(dst), "l"(src));
}
__device__ __forceinline__ uint32_t pack_h2(float a, float b) {
    __half2 h = __floats2half2_rn(a, b);
    return *(uint32_t*)&h;
}

// ---------------- fp16 tensor-core GEMM (4-stage cp.async pipeline) ----------------
constexpr int kStages = 4;
constexpr int kBM = 128, kBN = 128, kBKg = 32;
constexpr int kAP = 40, kBP = 136;
constexpr int kASTG = kBM * kAP;
constexpr int kBSTG = kBKg * kBP;
constexpr int kSmemHalves = kStages * (kASTG + kBSTG);
constexpr int kSmemBytes = kSmemHalves * 2;

// epi 0: Ch = alpha*acc (fp16)
// epi 1: Ch = gelu(acc + bias) (fp16)
// epi 2: Cf = resid + acc + (bias? bias : 0) (fp32)
__global__ __launch_bounds__(256, 2) void hgemm_kernel(
    int M, int N, int K, float alpha,
    const __half* __restrict__ A, const __half* __restrict__ Bm,
    const float* __restrict__ bias, const float* __restrict__ resid,
    float* __restrict__ Cf, __half* __restrict__ Ch, int epi) {
    extern __shared__ __half smem[];
    __half* As = smem;
    __half* Bs = smem + kStages * kASTG;

    int tid = threadIdx.x, lane = tid & 31, w = tid >> 5;
    int wr = w >> 2, wc = w & 3;
    int br = blockIdx.y, bc = blockIdx.x;
    const __half* Ap = A + (size_t)br * kBM * K;
    const __half* Bp = Bm + (size_t)bc * kBN;

    float acc[4][4][4];
#pragma unroll
    for (int i = 0; i < 4; i++)
#pragma unroll
        for (int j = 0; j < 4; j++)
#pragma unroll
            for (int r = 0; r < 4; r++) acc[i][j][r] = 0.f;

    int arow = tid >> 2, achk = tid & 3;
    int brow = tid >> 4, bchk = tid & 15;

    auto issue = [&](int stage, int k0) {
        uint32_t ab = smem_u32(As + stage * kASTG);
        uint32_t bb = smem_u32(Bs + stage * kBSTG);
#pragma unroll
        for (int p = 0; p < 2; p++) {
            int r = arow + p * 64;
            cp16(ab + (uint32_t)(r * kAP + achk * 8) * 2, Ap + (size_t)r * K + k0 + achk * 8);
        }
#pragma unroll
        for (int p = 0; p < 2; p++) {
            int r = brow + p * 16;
            cp16(bb + (uint32_t)(r * kBP + bchk * 8) * 2, Bp + (size_t)(k0 + r) * N + bchk * 8);
        }
        asm volatile("cp.async.commit_group;");
    };

    int nt = K / kBKg;
#pragma unroll
    for (int t = 0; t < kStages - 1; t++) issue(t, t * kBKg);

    int rowoff = (lane & 7) + ((lane >> 3) & 1) * 8;
    int seloff = (lane >> 4) * 8;

    for (int t = 0; t < nt; t++) {
        asm volatile("cp.async.wait_group %0;" :: "n"(kStages - 2));
        __syncthreads();
        int tn = t + kStages - 1;
        if (tn < nt) issue(tn % kStages, tn * kBKg);
        int buf = t % kStages;
        const __half* Ab = As + buf * kASTG;
        const __half* Bb = Bs + buf * kBSTG;
#pragma unroll
        for (int s = 0; s < 2; s++) {
            int k0 = s * 16;
            uint32_t af[4][4], bf[4][2];
#pragma unroll
            for (int i = 0; i < 4; i++) {
                int m0 = wr * 64 + i * 16;
                uint32_t addr = smem_u32(Ab + (m0 + rowoff) * kAP + k0 + seloff);
                ldsm_x4(af[i][0], af[i][1], af[i][2], af[i][3], addr);
            }
#pragma unroll
            for (int j2 = 0; j2 < 2; j2++) {
                int n0 = wc * 32 + j2 * 16;
                uint32_t addr = smem_u32(Bb + (k0 + rowoff) * kBP + n0 + seloff);
                uint32_t r0, r1, r2, r3;
                ldsm_x4t(r0, r1, r2, r3, addr);
                bf[j2 * 2][0] = r0; bf[j2 * 2][1] = r1;
                bf[j2 * 2 + 1][0] = r2; bf[j2 * 2 + 1][1] = r3;
            }
#pragma unroll
            for (int i = 0; i < 4; i++)
#pragma unroll
                for (int j = 0; j < 4; j++)
                    mma_f16(acc[i][j], af[i][0], af[i][1], af[i][2], af[i][3],
                            bf[j][0], bf[j][1]);
        }
    }

    int lq = lane >> 2, lr = lane & 3;
#pragma unroll
    for (int i = 0; i < 4; i++) {
        int r0 = br * kBM + wr * 64 + i * 16 + lq;
#pragma unroll
        for (int j = 0; j < 4; j++) {
            int col = bc * kBN + wc * 32 + j * 8 + lr * 2;
#pragma unroll
            for (int half = 0; half < 2; half++) {
                int row = r0 + half * 8;
                float v0 = acc[i][j][half * 2 + 0];
                float v1 = acc[i][j][half * 2 + 1];
                if (epi == 0) {
                    *(__half2*)(Ch + (size_t)row * N + col) =
                        __floats2half2_rn(v0 * alpha, v1 * alpha);
                } else if (epi == 1) {
                    v0 = gelu_f(v0 + bias[col]);
                    v1 = gelu_f(v1 + bias[col + 1]);
                    *(__half2*)(Ch + (size_t)row * N + col) = __floats2half2_rn(v0, v1);
                } else {
                    const float* rp = resid + (size_t)row * N + col;
                    float2 rr = *(const float2*)rp;
                    v0 += rr.x; v1 += rr.y;
                    if (bias) { v0 += bias[col]; v1 += bias[col + 1]; }
                    *(float2*)(Cf + (size_t)row * N + col) = make_float2(v0, v1);
                }
            }
        }
    }
}

// ---------------- ksum (fp16 in, fp32 out) ----------------
__global__ __launch_bounds__(512) void ksum_kernel(const __half* __restrict__ k,
                                                   float* __restrict__ ksum) {
    int bn = blockIdx.x;
    int tid = threadIdx.x;
    const __half* base = k + (size_t)bn * kBLK * kD + tid;
    float s = 0.f;
#pragma unroll 8
    for (int c = 0; c < kBLK; c++) s += __half2float(base[(size_t)c * kD]);
    ksum[bn * kD + tid] = s;
}

// ---------------- sinkhorn ----------------
__global__ __launch_bounds__(256) void sinkhorn_kernel(const float* __restrict__ ksum,
                                                       const float* __restrict__ sw,
                                                       const int* __restrict__ tokens,
                                                       float* __restrict__ perm_out,
                                                       float* __restrict__ smask_out) {
    int b = blockIdx.x / kH, h = blockIdx.x % kH;
    int tid = threadIdx.x;
    int n = tid >> 4, m = tid & 15;
    const float* kp = ksum + ((size_t)(b * kNB + n)) * kD + h * kDH;
    const float* wp = sw + (size_t)h * kDH * kNB + m;
    float la = 0.f;
#pragma unroll
    for (int d = 0; d < kDH; d++) la += kp[d] * wp[d * kNB];

    __shared__ float sm[16][17];
    for (int it = 0; it < 8; it++) {
        float mx = la;
#pragma unroll
        for (int o = 8; o >= 1; o >>= 1)
            mx = fmaxf(mx, __shfl_xor_sync(0xffffffffu, mx, o, 16));
        float e = expf(la - mx);
        float sum = e;
#pragma unroll
        for (int o = 8; o >= 1; o >>= 1)
            sum += __shfl_xor_sync(0xffffffffu, sum, o, 16);
        la = la - (mx + logf(sum));
        sm[n][m] = la;
        __syncthreads();
        float cmx = -1e30f;
#pragma unroll
        for (int i = 0; i < 16; i++) cmx = fmaxf(cmx, sm[i][m]);
        float cs = 0.f;
#pragma unroll
        for (int i = 0; i < 16; i++) cs += expf(sm[i][m] - cmx);
        la = la - (cmx + logf(cs));
        __syncthreads();
    }
    float p = expf(la);
    sm[n][m] = p;
    perm_out[((size_t)(b * kH + h) * kNB + n) * kNB + m] = p;
    __syncthreads();
    for (int idx = tid; idx < kNB * kBLK; idx += 256) {
        int nn = idx >> 7, c = idx & 127;
        float s = 0.f;
#pragma unroll
        for (int mm = 0; mm < 16; mm++) {
            float mb = (tokens[b * kS + mm * kBLK + c] > 0) ? 1.f : 0.f;
            s += sm[nn][mm] * mb;
        }
        smask_out[((size_t)(b * kH + h) * kNB + nn) * kBLK + c] = (s > 0.5f) ? 1.f : 0.f;
    }
}

// ---------------- sort-mix (fp16 in/out, fp32 accumulate) ----------------
__global__ __launch_bounds__(256) void sortmix_kernel(const float* __restrict__ perm,
                                                      const __half* __restrict__ k,
                                                      const __half* __restrict__ v,
                                                      __half* __restrict__ sk,
                                                      __half* __restrict__ sv) {
    int chunk = blockIdx.x;
    int h = blockIdx.y;
    int b = blockIdx.z;
    __shared__ float P[16][16];
    __shared__ float T[16][512];
    int tid = threadIdx.x;
    P[tid >> 4][tid & 15] = perm[(size_t)(b * kH + h) * 256 + tid];
    int cd0 = chunk * 512;

    for (int phase = 0; phase < 2; phase++) {
        const __half* src = phase ? v : k;
        __half* dst = phase ? sv : sk;
        __syncthreads();
        for (int idx = tid; idx < 16 * 512; idx += 256) {
            int m = idx >> 9;
            int j = idx & 511;
            int cd = cd0 + j;
            int c = cd >> 6, d = cd & 63;
            T[m][j] = __half2float(src[((size_t)(b * kS + m * kBLK + c)) * kD + h * kDH + d]);
        }
        __syncthreads();
        for (int idx = tid; idx < 16 * 512; idx += 256) {
            int n = idx >> 9;
            int j = idx & 511;
            float acc = 0.f;
#pragma unroll
            for (int m = 0; m < 16; m++) acc += P[n][m] * T[m][j];
            int cd = cd0 + j;
            int c = cd >> 6, d = cd & 63;
            dst[((size_t)(b * kS + n * kBLK + c)) * kD + h * kDH + d] = __float2half_rn(acc);
        }
    }
}

// ---------------- attention: mma.sync flash-style ----------------
// smem layout (halves, pitch 72): Q[128][72], K[256][72], V[256][72]; bias float[256]
constexpr int kAPitch = 72;
constexpr int kAttnQ = 128 * kAPitch;                    // 9216 halves
constexpr int kAttnKV = 256 * kAPitch;                   // 18432 halves
constexpr int kAttnSmem = (kAttnQ + 2 * kAttnKV) * 2 + 256 * 4 + 16;

__global__ __launch_bounds__(256, 1) void attn_kernel(
    const __half* __restrict__ q, const __half* __restrict__ k,
    const __half* __restrict__ v, const __half* __restrict__ sk,
    const __half* __restrict__ sv, const float* __restrict__ smask,
    const int* __restrict__ tokens, __half* __restrict__ o) {
    extern __shared__ char asm_raw[];
    __half* QS = (__half*)asm_raw;
    __half* KS = QS + kAttnQ;
    __half* VS = KS + kAttnKV;
    float* biasS = (float*)(VS + kAttnKV);

    int n0 = blockIdx.x, h = blockIdx.y, b = blockIdx.z;
    int tid = threadIdx.x, lane = tid & 31, wid = tid >> 5;

    // stage Q, Kcat, Vcat into smem (fp16, pitch 72)
    uint32_t qb = smem_u32(QS), kb = smem_u32(KS), vb = smem_u32(VS);
    for (int id = tid; id < 1024; id += 256) {
        int row = id >> 3, ch = id & 7;
        cp16(qb + (uint32_t)row * 144 + ch * 16,
             q + ((size_t)(b * kS + n0 * 128 + row)) * kD + h * 64 + ch * 8);
    }
    for (int id = tid; id < 2048; id += 256) {
        int row = id >> 3, ch = id & 7;
        const __half* src = (row < 128)
            ? k + ((size_t)(b * kS + n0 * 128 + row)) * kD + h * 64 + ch * 8
            : sk + ((size_t)(b * kS + n0 * 128 + row - 128)) * kD + h * 64 + ch * 8;
        cp16(kb + (uint32_t)row * 144 + ch * 16, src);
    }
    for (int id = tid; id < 2048; id += 256) {
        int row = id >> 3, ch = id & 7;
        const __half* src = (row < 128)
            ? v + ((size_t)(b * kS + n0 * 128 + row)) * kD + h * 64 + ch * 8
            : sv + ((size_t)(b * kS + n0 * 128 + row - 128)) * kD + h * 64 + ch * 8;
        cp16(vb + (uint32_t)row * 144 + ch * 16, src);
    }
    asm volatile("cp.async.commit_group;");
    for (int j = tid; j < 256; j += 256) {
        float mv;
        if (j < 128) mv = (tokens[b * kS + n0 * kBLK + j] > 0) ? 1.f : 0.f;
        else mv = smask[((size_t)(b * kH + h) * kNB + n0) * kBLK + (j - 128)];
        biasS[j] = (mv > 0.5f) ? 0.f : -1e9f;
    }
    asm volatile("cp.async.wait_group 0;");
    __syncthreads();

    int r0w = wid * 16;
    int rowoff = (lane & 7) + ((lane >> 3) & 1) * 8;   // trans pattern (A, V)
    int seloff = (lane >> 4) * 8;
    int browoff = (lane & 7) + ((lane >> 4) & 1) * 8;  // non-trans B pattern (K)
    int bseloff = ((lane >> 3) & 1) * 8;

    // Q fragments: 4 k-steps of 16
    uint32_t aq[4][4];
#pragma unroll
    for (int ks = 0; ks < 4; ks++) {
        uint32_t addr = smem_u32(QS + (r0w + rowoff) * kAPitch + ks * 16 + seloff);
        ldsm_x4(aq[ks][0], aq[ks][1], aq[ks][2], aq[ks][3], addr);
    }

    // S = Q @ K^T : [16 rows] x [256 keys]
    float sacc[16][8];
#pragma unroll
    for (int nt = 0; nt < 16; nt++)
#pragma unroll
        for (int c = 0; c < 8; c++) sacc[nt][c] = 0.f;

#pragma unroll
    for (int nt = 0; nt < 16; nt++) {
#pragma unroll
        for (int ks = 0; ks < 4; ks++) {
            uint32_t r0, r1, r2, r3;
            uint32_t addr = smem_u32(KS + (nt * 16 + browoff) * kAPitch + ks * 16 + bseloff);
            ldsm_x4(r0, r1, r2, r3, addr);
            mma_f16(&sacc[nt][0], aq[ks][0], aq[ks][1], aq[ks][2], aq[ks][3], r0, r1);
            mma_f16(&sacc[nt][4], aq[ks][0], aq[ks][1], aq[ks][2], aq[ks][3], r2, r3);
        }
    }

    // bias + softmax (full tile, rows lq and lq+8)
    int colbase = (lane & 3) * 2;
    float m0 = -1e30f, m1 = -1e30f;
#pragma unroll
    for (int nt = 0; nt < 16; nt++) {
#pragma unroll
        for (int sub = 0; sub < 2; sub++) {
            float2 bb = *(float2*)&biasS[nt * 16 + sub * 8 + colbase];
            sacc[nt][sub * 4 + 0] += bb.x;
            sacc[nt][sub * 4 + 1] += bb.y;
            sacc[nt][sub * 4 + 2] += bb.x;
            sacc[nt][sub * 4 + 3] += bb.y;
            m0 = fmaxf(m0, fmaxf(sacc[nt][sub * 4 + 0], sacc[nt][sub * 4 + 1]));
            m1 = fmaxf(m1, fmaxf(sacc[nt][sub * 4 + 2], sacc[nt][sub * 4 + 3]));
        }
    }
    m0 = fmaxf(m0, __shfl_xor_sync(0xffffffffu, m0, 1));
    m0 = fmaxf(m0, __shfl_xor_sync(0xffffffffu, m0, 2));
    m1 = fmaxf(m1, __shfl_xor_sync(0xffffffffu, m1, 1));
    m1 = fmaxf(m1, __shfl_xor_sync(0xffffffffu, m1, 2));
    float l0 = 0.f, l1 = 0.f;
#pragma unroll
    for (int nt = 0; nt < 16; nt++) {
#pragma unroll
        for (int sub = 0; sub < 2; sub++) {
            float p0 = __expf(sacc[nt][sub * 4 + 0] - m0);
            float p1 = __expf(sacc[nt][sub * 4 + 1] - m0);
            float p2 = __expf(sacc[nt][sub * 4 + 2] - m1);
            float p3 = __expf(sacc[nt][sub * 4 + 3] - m1);
            sacc[nt][sub * 4 + 0] = p0; sacc[nt][sub * 4 + 1] = p1;
            sacc[nt][sub * 4 + 2] = p2; sacc[nt][sub * 4 + 3] = p3;
            l0 += p0 + p1; l1 += p2 + p3;
        }
    }
    l0 += __shfl_xor_sync(0xffffffffu, l0, 1);
    l0 += __shfl_xor_sync(0xffffffffu, l0, 2);
    l1 += __shfl_xor_sync(0xffffffffu, l1, 1);
    l1 += __shfl_xor_sync(0xffffffffu, l1, 2);

    // O = P @ V : [16 rows] x [64 d]
    float oacc[8][4];
#pragma unroll
    for (int i = 0; i < 8; i++)
#pragma unroll
        for (int c = 0; c < 4; c++) oacc[i][c] = 0.f;

#pragma unroll
    for (int kt = 0; kt < 16; kt++) {
        uint32_t pa0 = pack_h2(sacc[kt][0], sacc[kt][1]);
        uint32_t pa1 = pack_h2(sacc[kt][2], sacc[kt][3]);
        uint32_t pa2 = pack_h2(sacc[kt][4], sacc[kt][5]);
        uint32_t pa3 = pack_h2(sacc[kt][6], sacc[kt][7]);
#pragma unroll
        for (int dg = 0; dg < 4; dg++) {
            uint32_t r0, r1, r2, r3;
            uint32_t addr = smem_u32(VS + (kt * 16 + rowoff) * kAPitch + dg * 16 + seloff);
            ldsm_x4t(r0, r1, r2, r3, addr);
            mma_f16(oacc[dg * 2], pa0, pa1, pa2, pa3, r0, r1);
            mma_f16(oacc[dg * 2 + 1], pa0, pa1, pa2, pa3, r2, r3);
        }
    }

    float inv0 = 1.f / l0, inv1 = 1.f / l1;
    int row0 = n0 * 128 + r0w + (lane >> 2);
#pragma unroll
    for (int dsub = 0; dsub < 8; dsub++) {
        int col = h * 64 + dsub * 8 + colbase;
        *(__half2*)(o + ((size_t)(b * kS + row0)) * kD + col) =
            __floats2half2_rn(oacc[dsub][0] * inv0, oacc[dsub][1] * inv0);
        *(__half2*)(o + ((size_t)(b * kS + row0 + 8)) * kD + col) =
            __floats2half2_rn(oacc[dsub][2] * inv1, oacc[dsub][3] * inv1);
    }
}

// ---------------- host orchestration ----------------
extern "C" void kernel_launch(void* const* d_in, const int* in_sizes, int n_in,
                              void* d_out, int out_size) {
    const int* tokens = (const int*)d_in[0];
    const float* embed = (const float*)d_in[1];
    const float* ln1_s = (const float*)d_in[2];
    const float* ln1_b = (const float*)d_in[3];
    const float* wq = (const float*)d_in[4];
    const float* wk = (const float*)d_in[5];
    const float* wv = (const float*)d_in[6];
    const float* wo = (const float*)d_in[7];
    const float* sortw = (const float*)d_in[8];
    const float* ln2_s = (const float*)d_in[9];
    const float* ln2_b = (const float*)d_in[10];
    const float* w1 = (const float*)d_in[11];
    const float* b1 = (const float*)d_in[12];
    const float* w2 = (const float*)d_in[13];
    const float* b2 = (const float*)d_in[14];
    const float* lnf_s = (const float*)d_in[15];
    const float* lnf_b = (const float*)d_in[16];
    float* out = (float*)d_out;

    float *x, *ksum, *perm, *smask;
    __half *qh, *kh, *vh, *skh, *svh, *hh, *oh, *mlph, *wqh, *wkh, *wvh, *woh, *w1h, *w2h;
    cudaGetSymbolAddress((void**)&x, g_x);
    cudaGetSymbolAddress((void**)&qh, g_qh);
    cudaGetSymbolAddress((void**)&kh, g_kh);
    cudaGetSymbolAddress((void**)&vh, g_vh);
    cudaGetSymbolAddress((void**)&skh, g_skh);
    cudaGetSymbolAddress((void**)&svh, g_svh);
    cudaGetSymbolAddress((void**)&ksum, g_ksum);
    cudaGetSymbolAddress((void**)&perm, g_perm);
    cudaGetSymbolAddress((void**)&smask, g_smask);
    cudaGetSymbolAddress((void**)&hh, g_hh);
    cudaGetSymbolAddress((void**)&oh, g_oh);
    cudaGetSymbolAddress((void**)&mlph, g_mlph);
    cudaGetSymbolAddress((void**)&wqh, g_wq_h);
    cudaGetSymbolAddress((void**)&wkh, g_wk_h);
    cudaGetSymbolAddress((void**)&wvh, g_wv_h);
    cudaGetSymbolAddress((void**)&woh, g_wo_h);
    cudaGetSymbolAddress((void**)&w1h, g_w1_h);
    cudaGetSymbolAddress((void**)&w2h, g_w2_h);

    cudaFuncSetAttribute(hgemm_kernel, cudaFuncAttributeMaxDynamicSharedMemorySize,
                         kSmemBytes);
    cudaFuncSetAttribute(attn_kernel, cudaFuncAttributeMaxDynamicSharedMemorySize,
                         kAttnSmem);

    int nW = kL * kD * kD;
    int nM = kL * kD * kMLP;
    {
        dim3 g(nM / 4 / 256, 6);
        f2h6_kernel<<<g, 256>>>(wq, wk, wv, wo, w1, w2,
                                wqh, wkh, wvh, woh, w1h, w2h, nW, nM);
    }

    embed_pe_kernel<<<(kBSD + 255) / 256, 256>>>(tokens, embed, x);

    const float qscale = 1.0f / 8.0f;
    dim3 gD(kD / 128, kBS / 128);
    dim3 gM(kMLP / 128, kBS / 128);

    for (int l = 0; l < kL; l++) {
        __half* wq_l = wqh + (size_t)l * kD * kD;
        __half* wk_l = wkh + (size_t)l * kD * kD;
        __half* wv_l = wvh + (size_t)l * kD * kD;
        __half* wo_l = woh + (size_t)l * kD * kD;
        const float* sw_l = sortw + (size_t)l * kH * kDH * kNB;
        __half* w1_l = w1h + (size_t)l * kD * kMLP;
        const float* b1_l = b1 + (size_t)l * kMLP;
        __half* w2_l = w2h + (size_t)l * kMLP * kD;
        const float* b2_l = b2 + (size_t)l * kD;

        ln_kernel<<<kBS, 128>>>(x, ln1_s + l * kD, ln1_b + l * kD, hh, nullptr);
        hgemm_kernel<<<gD, 256, kSmemBytes>>>(kBS, kD, kD, qscale, hh, wq_l, nullptr, nullptr, nullptr, qh, 0);
        hgemm_kernel<<<gD, 256, kSmemBytes>>>(kBS, kD, kD, 1.0f, hh, wk_l, nullptr, nullptr, nullptr, kh, 0);
        hgemm_kernel<<<gD, 256, kSmemBytes>>>(kBS, kD, kD, 1.0f, hh, wv_l, nullptr, nullptr, nullptr, vh, 0);

        ksum_kernel<<<kB * kNB, 512>>>(kh, ksum);
        sinkhorn_kernel<<<kB * kH, 256>>>(ksum, sw_l, tokens, perm, smask);
        sortmix_kernel<<<dim3(16, kH, kB), 256>>>(perm, kh, vh, skh, svh);

        attn_kernel<<<dim3(kNB, kH, kB), 256, kAttnSmem>>>(qh, kh, vh, skh, svh,
                                                           smask, tokens, oh);

        // x = x + o @ wo
        hgemm_kernel<<<gD, 256, kSmemBytes>>>(kBS, kD, kD, 1.0f, oh, wo_l, nullptr, x, x, nullptr, 2);

        // MLP
        ln_kernel<<<kBS, 128>>>(x, ln2_s + l * kD, ln2_b + l * kD, hh, nullptr);
        hgemm_kernel<<<gM, 256, kSmemBytes>>>(kBS, kMLP, kD, 1.0f, hh, w1_l, b1_l, nullptr, nullptr, mlph, 1);
        hgemm_kernel<<<gD, 256, kSmemBytes>>>(kBS, kD, kMLP, 1.0f, mlph, w2_l, b2_l, x, x, nullptr, 2);
    }

    ln_kernel<<<kBS, 128>>>(x, lnf_s, lnf_b, nullptr, out);
}